// round 3
// baseline (speedup 1.0000x reference)
#include <cuda_runtime.h>
#include <math.h>

#define BB   512
#define SS   200
#define DD   1024
#define PP   256
#define G4   4096
#define DIN  1280

// ---------------- scratch (device globals; no allocation allowed) ----------------
__device__ float g_Weff[G4 * 16];            // (4096,16)  folded input weights
__device__ float g_bias[G4];                 // folded bias
__device__ float g_Zc[(size_t)BB * G4];      // (512,4096) context + bias term
__device__ float g_c[(size_t)BB * DD];       // cell state
__device__ float g_hraw[(size_t)BB * DD];    // pre-projection hidden
__device__ float g_h[2][(size_t)BB * PP];    // projected hidden ping-pong
__device__ float g_part[4][(size_t)BB * PP]; // split-K partials for projection
__device__ float g_hs[(size_t)BB * SS * PP]; // all projected hiddens (for heads)

// ---------------- fast activations ----------------
__device__ __forceinline__ float sigf(float x) {
    return 1.0f / (1.0f + __expf(-x));
}
__device__ __forceinline__ float tanh_f(float x) {
    float e = __expf(-2.0f * fabsf(x));
    float t = (1.0f - e) / (1.0f + e);
    return copysignf(t, x);
}

// ---------------- prologue 1: W_eff (4096x16) and folded bias ----------------
// W_eff[j][c] = sum_k W_ih[j][k] * Wx[k][c]   (Wx = [W_cmd | W_crd], 1024x16)
// bias[j] = sum_k W_ih[j][k]*(b_cmd[k]+b_crd[k]) + b_ih[j] + b_hh[j]
__global__ __launch_bounds__(128) void prep_weff(
    const float* __restrict__ W_ih, const float* __restrict__ b_ih,
    const float* __restrict__ W_cmd, const float* __restrict__ b_cmd,
    const float* __restrict__ W_crd, const float* __restrict__ b_crd,
    const float* __restrict__ b_hh)
{
    int j = blockIdx.x;
    int t = threadIdx.x;
    __shared__ float red[17][128];

    float acc[17];
#pragma unroll
    for (int c = 0; c < 17; c++) acc[c] = 0.0f;

    const float* wrow = W_ih + (size_t)j * DIN;
    for (int k = t; k < DD; k += 128) {
        float w = wrow[k];
#pragma unroll
        for (int c = 0; c < 10; c++) acc[c]      = fmaf(w, W_cmd[k * 10 + c], acc[c]);
#pragma unroll
        for (int c = 0; c < 6; c++)  acc[10 + c] = fmaf(w, W_crd[k * 6 + c], acc[10 + c]);
        acc[16] = fmaf(w, b_cmd[k] + b_crd[k], acc[16]);
    }
#pragma unroll
    for (int c = 0; c < 17; c++) red[c][t] = acc[c];
    __syncthreads();
    for (int off = 64; off > 0; off >>= 1) {
        if (t < off) {
#pragma unroll
            for (int c = 0; c < 17; c++) red[c][t] += red[c][t + off];
        }
        __syncthreads();
    }
    if (t == 0) {
#pragma unroll
        for (int c = 0; c < 16; c++) g_Weff[j * 16 + c] = red[c][0];
        g_bias[j] = red[16][0] + b_ih[j] + b_hh[j];
    }
}

// ---------------- prologue 2: Zc = ctx @ W_ih[:,1024:]^T + bias ----------------
// M=512, N=4096, K=256. Tiles 64x64, thread 4x4.
__global__ __launch_bounds__(256) void prep_zc(
    const float* __restrict__ ctx, const float* __restrict__ W_ih)
{
    __shared__ float sA[64][17];
    __shared__ float sB[64][17];
    int n0 = blockIdx.x * 64;
    int m0 = blockIdx.y * 64;
    int tid = threadIdx.x, tx = tid & 15, ty = tid >> 4;

    float acc[4][4];
#pragma unroll
    for (int i = 0; i < 4; i++)
#pragma unroll
        for (int j = 0; j < 4; j++) acc[i][j] = 0.0f;

    for (int k0 = 0; k0 < 256; k0 += 16) {
        __syncthreads();
#pragma unroll
        for (int q = 0; q < 4; q++) {
            int e = q * 256 + tid;
            int r = e >> 4, c = e & 15;
            sA[r][c] = ctx[(size_t)(m0 + r) * 256 + k0 + c];
            sB[r][c] = W_ih[(size_t)(n0 + r) * DIN + 1024 + k0 + c];
        }
        __syncthreads();
#pragma unroll
        for (int kk = 0; kk < 16; kk++) {
            float a[4], b[4];
#pragma unroll
            for (int i = 0; i < 4; i++) a[i] = sA[ty + 16 * i][kk];
#pragma unroll
            for (int j = 0; j < 4; j++) b[j] = sB[tx + 16 * j][kk];
#pragma unroll
            for (int i = 0; i < 4; i++)
#pragma unroll
                for (int j = 0; j < 4; j++) acc[i][j] = fmaf(a[i], b[j], acc[i][j]);
        }
    }
#pragma unroll
    for (int i = 0; i < 4; i++) {
        int m = m0 + ty + 16 * i;
#pragma unroll
        for (int j = 0; j < 4; j++) {
            int n = n0 + tx + 16 * j;
            g_Zc[(size_t)m * G4 + n] = acc[i][j] + g_bias[n];
        }
    }
}

// ---------------- init state (must re-run every launch: determinism) ----------------
__global__ void init_state()
{
    int i = blockIdx.x * blockDim.x + threadIdx.x;
    if (i < BB * DD) g_c[i] = 0.0f;
    if (i < BB * PP) g_h[0][i] = 0.0f;
}

// ---------------- per-step gates: gates = Zc + x16_t@W_eff^T + h@W_hh^T ----------------
// grid (16 j-tiles, 8 m-tiles), block 256. Tile: 64 m x 64 j x 4 gates, thread 4x4x4.
__global__ __launch_bounds__(256) void lstm_gates(
    const float* __restrict__ x, const float* __restrict__ W_hh, int t, int hsel)
{
    __shared__ float sh[64][17];
    __shared__ float sw[4][64][17];
    __shared__ float sx[64][16];
    __shared__ float swe[256][17]; // [g*64 + jl][k]

    const float* __restrict__ hprev = g_h[hsel];
    int j0 = blockIdx.x * 64, m0 = blockIdx.y * 64;
    int tid = threadIdx.x, tx = tid & 15, ty = tid >> 4;

    // stage x16 tile and W_eff tile
#pragma unroll
    for (int q = 0; q < 4; q++) {
        int e = q * 256 + tid;
        int r = e >> 4, c = e & 15;
        sx[r][c] = x[((size_t)(m0 + r) * SS + t) * 16 + c];
    }
#pragma unroll
    for (int q = 0; q < 16; q++) {
        int e = q * 256 + tid;
        int row = e >> 4, c = e & 15;       // row = g*64 + jl
        int g = row >> 6, jl = row & 63;
        swe[row][c] = g_Weff[(size_t)((g << 10) + j0 + jl) * 16 + c];
    }
    __syncthreads();

    float acc[4][4][4];
#pragma unroll
    for (int g = 0; g < 4; g++)
#pragma unroll
        for (int mi = 0; mi < 4; mi++)
#pragma unroll
            for (int ji = 0; ji < 4; ji++) {
                int ml = ty + 16 * mi;
                int jl = tx + 16 * ji;
                float a = g_Zc[(size_t)(m0 + ml) * G4 + (g << 10) + j0 + jl];
#pragma unroll
                for (int k = 0; k < 16; k++)
                    a = fmaf(sx[ml][k], swe[g * 64 + jl][k], a);
                acc[g][mi][ji] = a;
            }

    // main K loop over h @ W_hh^T  (K = 256)
    for (int k0 = 0; k0 < 256; k0 += 16) {
        __syncthreads();
#pragma unroll
        for (int q = 0; q < 4; q++) {
            int e = q * 256 + tid;
            int r = e >> 4, c = e & 15;
            sh[r][c] = hprev[(size_t)(m0 + r) * PP + k0 + c];
        }
#pragma unroll
        for (int q = 0; q < 16; q++) {
            int e = q * 256 + tid;
            int g = e >> 10, rr = (e >> 4) & 63, c = e & 15;
            sw[g][rr][c] = W_hh[(size_t)((g << 10) + j0 + rr) * PP + k0 + c];
        }
        __syncthreads();
#pragma unroll
        for (int kk = 0; kk < 16; kk++) {
            float hv[4];
#pragma unroll
            for (int mi = 0; mi < 4; mi++) hv[mi] = sh[ty + 16 * mi][kk];
            float wv[4][4];
#pragma unroll
            for (int g = 0; g < 4; g++)
#pragma unroll
                for (int ji = 0; ji < 4; ji++) wv[g][ji] = sw[g][tx + 16 * ji][kk];
#pragma unroll
            for (int g = 0; g < 4; g++)
#pragma unroll
                for (int mi = 0; mi < 4; mi++)
#pragma unroll
                    for (int ji = 0; ji < 4; ji++)
                        acc[g][mi][ji] = fmaf(hv[mi], wv[g][ji], acc[g][mi][ji]);
        }
    }

    // LSTM cell epilogue: c, h_raw
#pragma unroll
    for (int mi = 0; mi < 4; mi++) {
        int m = m0 + ty + 16 * mi;
#pragma unroll
        for (int ji = 0; ji < 4; ji++) {
            int j = j0 + tx + 16 * ji;
            float iv = acc[0][mi][ji];
            float fv = acc[1][mi][ji];
            float gv = acc[2][mi][ji];
            float ov = acc[3][mi][ji];
            size_t idx = (size_t)m * DD + j;
            float cn = sigf(fv) * g_c[idx] + sigf(iv) * tanh_f(gv);
            g_c[idx] = cn;
            g_hraw[idx] = sigf(ov) * tanh_f(cn);
        }
    }
}

// ---------------- per-step projection, stage 1: split-K partials ----------------
// part[kc][m][r] = sum_{j in chunk kc (256 wide)} hraw[m][j] * W_hr[r][j]
// grid (4 r-tiles, 8 m-tiles, 4 k-chunks) = 128 blocks (one wave), tile 64x64.
__global__ __launch_bounds__(256) void proj_partial(const float* __restrict__ W_hr)
{
    __shared__ float sA[64][17];
    __shared__ float sB[64][17];
    int r0 = blockIdx.x * 64, m0 = blockIdx.y * 64, kc = blockIdx.z;
    int tid = threadIdx.x, tx = tid & 15, ty = tid >> 4;

    float acc[4][4];
#pragma unroll
    for (int i = 0; i < 4; i++)
#pragma unroll
        for (int j = 0; j < 4; j++) acc[i][j] = 0.0f;

    int kend = kc * 256 + 256;
    for (int k0 = kc * 256; k0 < kend; k0 += 16) {
        __syncthreads();
#pragma unroll
        for (int q = 0; q < 4; q++) {
            int e = q * 256 + tid;
            int r = e >> 4, c = e & 15;
            sA[r][c] = g_hraw[(size_t)(m0 + r) * DD + k0 + c];
            sB[r][c] = W_hr[(size_t)(r0 + r) * DD + k0 + c];
        }
        __syncthreads();
#pragma unroll
        for (int kk = 0; kk < 16; kk++) {
            float a[4], b[4];
#pragma unroll
            for (int i = 0; i < 4; i++) a[i] = sA[ty + 16 * i][kk];
#pragma unroll
            for (int j = 0; j < 4; j++) b[j] = sB[tx + 16 * j][kk];
#pragma unroll
            for (int i = 0; i < 4; i++)
#pragma unroll
                for (int j = 0; j < 4; j++) acc[i][j] = fmaf(a[i], b[j], acc[i][j]);
        }
    }
#pragma unroll
    for (int i = 0; i < 4; i++) {
        int m = m0 + ty + 16 * i;
#pragma unroll
        for (int j = 0; j < 4; j++) {
            int r = r0 + tx + 16 * j;
            g_part[kc][(size_t)m * PP + r] = acc[i][j];
        }
    }
}

// ---------------- per-step projection, stage 2: deterministic reduce ----------------
__global__ void proj_reduce(int t, int hnext_sel)
{
    int i = blockIdx.x * blockDim.x + threadIdx.x;
    if (i >= BB * PP) return;
    float s = 0.0f;
#pragma unroll
    for (int kc = 0; kc < 4; kc++) s += g_part[kc][i];
    g_h[hnext_sel][i] = s;
    int m = i >> 8, r = i & 255;
    g_hs[((size_t)m * SS + t) * PP + r] = s;
}

// ---------------- output heads: LN + command logits + coords (warp per row) ----------------
__global__ __launch_bounds__(256) void head_kernel(
    const float* __restrict__ ln_g, const float* __restrict__ ln_b,
    const float* __restrict__ W_oc, const float* __restrict__ b_oc,
    const float* __restrict__ W_ox, const float* __restrict__ b_ox,
    const float* __restrict__ scale_p, float* __restrict__ out)
{
    int gw = (blockIdx.x * 256 + threadIdx.x) >> 5;
    int lane = threadIdx.x & 31;
    if (gw >= BB * SS) return;

    const float* hrow = g_hs + (size_t)gw * PP;
    float v[8];
#pragma unroll
    for (int q = 0; q < 2; q++) {
        float4 f = *reinterpret_cast<const float4*>(hrow + lane * 8 + q * 4);
        v[q * 4 + 0] = f.x; v[q * 4 + 1] = f.y; v[q * 4 + 2] = f.z; v[q * 4 + 3] = f.w;
    }
    float s = 0.0f, s2 = 0.0f;
#pragma unroll
    for (int e = 0; e < 8; e++) { s += v[e]; s2 = fmaf(v[e], v[e], s2); }
#pragma unroll
    for (int o = 16; o > 0; o >>= 1) {
        s  += __shfl_xor_sync(0xFFFFFFFFu, s, o);
        s2 += __shfl_xor_sync(0xFFFFFFFFu, s2, o);
    }
    float mean = s * (1.0f / 256.0f);
    float var = s2 * (1.0f / 256.0f) - mean * mean;
    float rstd = rsqrtf(var + 1e-5f);

    float hn[8];
#pragma unroll
    for (int e = 0; e < 8; e++) {
        int c = lane * 8 + e;
        hn[e] = (v[e] - mean) * rstd * ln_g[c] + ln_b[c];
    }

    float lgs[10];
#pragma unroll
    for (int cc = 0; cc < 10; cc++) {
        float p = 0.0f;
#pragma unroll
        for (int e = 0; e < 8; e++)
            p = fmaf(hn[e], W_oc[cc * 256 + lane * 8 + e], p);
#pragma unroll
        for (int o = 16; o > 0; o >>= 1) p += __shfl_xor_sync(0xFFFFFFFFu, p, o);
        p += b_oc[cc];
        lgs[cc] = p;
        if (lane == cc) out[(size_t)gw * 10 + cc] = p;
    }

    float csc = *scale_p;
    float* outc = out + (size_t)BB * SS * 10;
#pragma unroll
    for (int q = 0; q < 6; q++) {
        float p = 0.0f;
#pragma unroll
        for (int e = 0; e < 8; e++)
            p = fmaf(hn[e], W_ox[q * 266 + lane * 8 + e], p);
#pragma unroll
        for (int o = 16; o > 0; o >>= 1) p += __shfl_xor_sync(0xFFFFFFFFu, p, o);
#pragma unroll
        for (int cc = 0; cc < 10; cc++)
            p = fmaf(lgs[cc], W_ox[q * 266 + 256 + cc], p);
        p += b_ox[q];
        float z = tanh_f(p * csc);
        if (lane == q) outc[(size_t)gw * 6 + q] = z;
    }
}

// ---------------- launch ----------------
extern "C" void kernel_launch(void* const* d_in, const int* in_sizes, int n_in,
                              void* d_out, int out_size)
{
    const float* x      = (const float*)d_in[0];
    const float* ctx    = (const float*)d_in[1];
    const float* W_cmd  = (const float*)d_in[2];
    const float* b_cmd  = (const float*)d_in[3];
    const float* W_crd  = (const float*)d_in[4];
    const float* b_crd  = (const float*)d_in[5];
    const float* W_ih   = (const float*)d_in[6];
    const float* b_ih   = (const float*)d_in[7];
    const float* W_hh   = (const float*)d_in[8];
    const float* b_hh   = (const float*)d_in[9];
    const float* W_hr   = (const float*)d_in[10];
    const float* ln_g   = (const float*)d_in[11];
    const float* ln_b   = (const float*)d_in[12];
    const float* W_oc   = (const float*)d_in[13];
    const float* b_oc   = (const float*)d_in[14];
    const float* W_ox   = (const float*)d_in[15];
    const float* b_ox   = (const float*)d_in[16];
    const float* cscale = (const float*)d_in[17];
    float* out = (float*)d_out;

    prep_weff<<<G4, 128>>>(W_ih, b_ih, W_cmd, b_cmd, W_crd, b_crd, b_hh);
    prep_zc<<<dim3(G4 / 64, BB / 64), 256>>>(ctx, W_ih);
    init_state<<<(BB * DD + 255) / 256, 256>>>();

    for (int t = 0; t < SS; t++) {
        lstm_gates<<<dim3(16, 8), 256>>>(x, W_hh, t, t & 1);
        proj_partial<<<dim3(4, 8, 4), 256>>>(W_hr);
        proj_reduce<<<(BB * PP + 255) / 256, 256>>>(t, (t + 1) & 1);
    }

    head_kernel<<<(BB * SS * 32 + 255) / 256, 256>>>(
        ln_g, ln_b, W_oc, b_oc, W_ox, b_ox, cscale, out);
}

// round 5
// speedup vs baseline: 1.3796x; 1.3796x over previous
#include <cuda_runtime.h>
#include <cuda_bf16.h>
#include <cstdint>
#include <math.h>

#define BB   512
#define SS   200
#define DD   1024
#define PP   256
#define G4   4096
#define DIN  1280
#define KPAD 24   // padded k-stride (bf16 elems) for conflict-free ldmatrix (48B)

// ---------------- scratch (device globals; no allocation allowed) ----------------
__device__ float g_bias[G4];                                   // folded bias
__device__ float g_Zc[(size_t)BB * G4];                        // (512,4096) context+bias
__device__ float g_c[(size_t)BB * DD];                         // cell state fp32
__device__ __align__(16) __nv_bfloat16 g_hraw_hi[(size_t)BB * DD];  // pre-proj hidden (split)
__device__ __align__(16) __nv_bfloat16 g_hraw_lo[(size_t)BB * DD];
__device__ __align__(16) __nv_bfloat16 g_h_hi[(size_t)BB * PP];     // projected hidden (split)
__device__ __align__(16) __nv_bfloat16 g_h_lo[(size_t)BB * PP];
__device__ float g_hs[(size_t)BB * SS * PP];                   // all projected hiddens (heads)
// packed, pre-split weights (mma tile layouts)
__device__ __align__(16) __nv_bfloat16 g_Wt_hi[16 * 16 * 256 * 16]; // [jt][kc][row=g*64+jl][kk]
__device__ __align__(16) __nv_bfloat16 g_Wt_lo[16 * 16 * 256 * 16];
__device__ __align__(16) __nv_bfloat16 g_Weff_hi[16 * 256 * 16];    // [jt][row][kk]
__device__ __align__(16) __nv_bfloat16 g_Weff_lo[16 * 256 * 16];
__device__ __align__(16) __nv_bfloat16 g_Whr_hi[4 * 64 * 64 * 16];  // [rt][kc][rl][kk]
__device__ __align__(16) __nv_bfloat16 g_Whr_lo[4 * 64 * 64 * 16];

// ---------------- helpers ----------------
__device__ __forceinline__ float sigf(float x) { return 1.0f / (1.0f + __expf(-x)); }
__device__ __forceinline__ float tanh_f(float x) {
    float e = __expf(-2.0f * fabsf(x));
    float t = (1.0f - e) / (1.0f + e);
    return copysignf(t, x);
}
__device__ __forceinline__ void split_bf16(float x, __nv_bfloat16& hi, __nv_bfloat16& lo) {
    hi = __float2bfloat16(x);
    lo = __float2bfloat16(x - __bfloat162float(hi));
}
__device__ __forceinline__ void ldsm_x4(uint32_t& r0, uint32_t& r1, uint32_t& r2, uint32_t& r3,
                                        const __nv_bfloat16* p) {
    uint32_t a = (uint32_t)__cvta_generic_to_shared(p);
    asm volatile("ldmatrix.sync.aligned.m8n8.x4.shared.b16 {%0,%1,%2,%3}, [%4];"
                 : "=r"(r0), "=r"(r1), "=r"(r2), "=r"(r3) : "r"(a));
}
__device__ __forceinline__ void mma_bf16(float* d, const uint32_t* a, uint32_t b0, uint32_t b1) {
    asm volatile("mma.sync.aligned.m16n8k16.row.col.f32.bf16.bf16.f32 "
                 "{%0,%1,%2,%3}, {%4,%5,%6,%7}, {%8,%9}, {%0,%1,%2,%3};"
                 : "+f"(d[0]), "+f"(d[1]), "+f"(d[2]), "+f"(d[3])
                 : "r"(a[0]), "r"(a[1]), "r"(a[2]), "r"(a[3]), "r"(b0), "r"(b1));
}

// ---------------- prologue 1: W_eff (split+packed) and folded bias ----------------
__global__ __launch_bounds__(128) void prep_weff(
    const float* __restrict__ W_ih, const float* __restrict__ b_ih,
    const float* __restrict__ W_cmd, const float* __restrict__ b_cmd,
    const float* __restrict__ W_crd, const float* __restrict__ b_crd,
    const float* __restrict__ b_hh)
{
    int j = blockIdx.x;            // 0..4095
    int t = threadIdx.x;
    __shared__ float red[17][128];

    float acc[17];
#pragma unroll
    for (int c = 0; c < 17; c++) acc[c] = 0.0f;

    const float* wrow = W_ih + (size_t)j * DIN;
    for (int k = t; k < DD; k += 128) {
        float w = wrow[k];
#pragma unroll
        for (int c = 0; c < 10; c++) acc[c]      = fmaf(w, W_cmd[k * 10 + c], acc[c]);
#pragma unroll
        for (int c = 0; c < 6; c++)  acc[10 + c] = fmaf(w, W_crd[k * 6 + c], acc[10 + c]);
        acc[16] = fmaf(w, b_cmd[k] + b_crd[k], acc[16]);
    }
#pragma unroll
    for (int c = 0; c < 17; c++) red[c][t] = acc[c];
    __syncthreads();
    for (int off = 64; off > 0; off >>= 1) {
        if (t < off) {
#pragma unroll
            for (int c = 0; c < 17; c++) red[c][t] += red[c][t + off];
        }
        __syncthreads();
    }
    if (t == 0) {
        int g  = j >> 10;
        int jj = j & 1023;
        int jt = jj >> 6;
        int jl = jj & 63;
        int row = g * 64 + jl;
        size_t base = ((size_t)jt * 256 + row) * 16;
#pragma unroll
        for (int c = 0; c < 16; c++) {
            __nv_bfloat16 hi, lo;
            split_bf16(red[c][0], hi, lo);
            g_Weff_hi[base + c] = hi;
            g_Weff_lo[base + c] = lo;
        }
        g_bias[j] = red[16][0] + b_ih[j] + b_hh[j];
    }
}

// ---------------- prologue 2: Zc = ctx @ W_ih[:,1024:]^T + bias ----------------
__global__ __launch_bounds__(256) void prep_zc(
    const float* __restrict__ ctx, const float* __restrict__ W_ih)
{
    __shared__ float sA[64][17];
    __shared__ float sB[64][17];
    int n0 = blockIdx.x * 64;
    int m0 = blockIdx.y * 64;
    int tid = threadIdx.x;
    int tx = tid & 15;
    int ty = tid >> 4;

    float acc[4][4];
#pragma unroll
    for (int i = 0; i < 4; i++)
#pragma unroll
        for (int j = 0; j < 4; j++) acc[i][j] = 0.0f;

    for (int k0 = 0; k0 < 256; k0 += 16) {
        __syncthreads();
#pragma unroll
        for (int q = 0; q < 4; q++) {
            int e = q * 256 + tid;
            int r = e >> 4;
            int c = e & 15;
            sA[r][c] = ctx[(size_t)(m0 + r) * 256 + k0 + c];
            sB[r][c] = W_ih[(size_t)(n0 + r) * DIN + 1024 + k0 + c];
        }
        __syncthreads();
#pragma unroll
        for (int kk = 0; kk < 16; kk++) {
            float a[4];
            float b[4];
#pragma unroll
            for (int i = 0; i < 4; i++) a[i] = sA[ty + 16 * i][kk];
#pragma unroll
            for (int j = 0; j < 4; j++) b[j] = sB[tx + 16 * j][kk];
#pragma unroll
            for (int i = 0; i < 4; i++)
#pragma unroll
                for (int j = 0; j < 4; j++) acc[i][j] = fmaf(a[i], b[j], acc[i][j]);
        }
    }
#pragma unroll
    for (int i = 0; i < 4; i++) {
        int m = m0 + ty + 16 * i;
#pragma unroll
        for (int j = 0; j < 4; j++) {
            int n = n0 + tx + 16 * j;
            g_Zc[(size_t)m * G4 + n] = acc[i][j] + g_bias[n];
        }
    }
}

// ---------------- prologue 3: split + tile-pack W_hh ----------------
__global__ __launch_bounds__(256) void prep_whh_split(const float* __restrict__ W_hh)
{
    int idx = blockIdx.x * 256 + threadIdx.x;     // 0 .. 1,048,575
    int kk  = idx & 15;
    int row = (idx >> 4) & 255;
    int kc  = (idx >> 12) & 15;
    int jt  = idx >> 16;
    int g = row >> 6;
    int jl = row & 63;
    float w = W_hh[(size_t)((g << 10) + (jt << 6) + jl) * 256 + (kc << 4) + kk];
    __nv_bfloat16 hi, lo;
    split_bf16(w, hi, lo);
    g_Wt_hi[idx] = hi;
    g_Wt_lo[idx] = lo;
}

// ---------------- prologue 4: split + tile-pack W_hr ----------------
__global__ __launch_bounds__(256) void prep_whr_split(const float* __restrict__ W_hr)
{
    int idx = blockIdx.x * 256 + threadIdx.x;     // 0 .. 262,143
    int kk = idx & 15;
    int rl = (idx >> 4) & 63;
    int kc = (idx >> 10) & 63;
    int rt = idx >> 16;
    float w = W_hr[(size_t)((rt << 6) + rl) * 1024 + (kc << 4) + kk];
    __nv_bfloat16 hi, lo;
    split_bf16(w, hi, lo);
    g_Whr_hi[idx] = hi;
    g_Whr_lo[idx] = lo;
}

// ---------------- init state ----------------
__global__ void init_state()
{
    int i = blockIdx.x * blockDim.x + threadIdx.x;
    if (i < BB * DD) g_c[i] = 0.0f;
    if (i < BB * PP) {
        g_h_hi[i] = __float2bfloat16(0.0f);
        g_h_lo[i] = __float2bfloat16(0.0f);
    }
}

// ---------------- per-step gates (tensor core, bf16 split) ----------------
// grid (16 jt, 8 mt), 256 threads = 8 warps (2 m-warps x 4 j-warps).
// Block tile: 64m x 64j x 4 gates. K-loop: 16 chunks of h@W_hh + 1 chunk of x@W_eff.
__global__ __launch_bounds__(256) void lstm_gates(const float* __restrict__ x, int t)
{
    __shared__ __align__(16) __nv_bfloat16 sh_hi[64 * KPAD];
    __shared__ __align__(16) __nv_bfloat16 sh_lo[64 * KPAD];
    __shared__ __align__(16) __nv_bfloat16 sw_hi[256 * KPAD];
    __shared__ __align__(16) __nv_bfloat16 sw_lo[256 * KPAD];

    int jt = blockIdx.x;
    int mt = blockIdx.y;
    int m0 = mt * 64;
    int j0 = jt * 64;
    int tid = threadIdx.x;
    int wid = tid >> 5;
    int lane = tid & 31;
    int wm = wid >> 2;
    int wj = wid & 3;
    int gid = lane >> 2;
    int tig = lane & 3;
    int lr = lane & 15;
    int lkh = lane >> 4;       // ldmatrix row / k-half select

    float acc[4][2][2][4];
#pragma unroll
    for (int g = 0; g < 4; g++)
#pragma unroll
        for (int mi = 0; mi < 2; mi++)
#pragma unroll
            for (int ni = 0; ni < 2; ni++)
#pragma unroll
                for (int q = 0; q < 4; q++) acc[g][mi][ni][q] = 0.0f;

    for (int it = 0; it < 17; ++it) {
        // ---- stage W tile (256 rows x 16 k, hi+lo) ----
        const uint4* wh;
        const uint4* wl;
        if (it < 16) {
            size_t base = (size_t)(jt * 16 + it) * 256 * 16;
            wh = (const uint4*)(g_Wt_hi + base);
            wl = (const uint4*)(g_Wt_lo + base);
        } else {
            size_t base = (size_t)jt * 256 * 16;
            wh = (const uint4*)(g_Weff_hi + base);
            wl = (const uint4*)(g_Weff_lo + base);
        }
#pragma unroll
        for (int q = 0; q < 2; q++) {
            int u = tid + (q << 8);
            int row = u >> 1;
            int hf = u & 1;
            *(uint4*)&sw_hi[row * KPAD + hf * 8] = wh[u];
            *(uint4*)&sw_lo[row * KPAD + hf * 8] = wl[u];
        }
        // ---- stage A tile (64 m x 16 k) ----
        if (it < 16) {
#pragma unroll
            for (int q = 0; q < 2; q++) {
                int u = tid + (q << 8);        // 0..511
                int row = u >> 3;
                int cp = u & 7;
                const uint32_t* srch = (const uint32_t*)(g_h_hi + (size_t)(m0 + row) * PP + it * 16);
                const uint32_t* srcl = (const uint32_t*)(g_h_lo + (size_t)(m0 + row) * PP + it * 16);
                *(uint32_t*)&sh_hi[row * KPAD + cp * 2] = srch[cp];
                *(uint32_t*)&sh_lo[row * KPAD + cp * 2] = srcl[cp];
            }
        } else {
#pragma unroll
            for (int q = 0; q < 4; q++) {
                int e = tid + (q << 8);        // 0..1023
                int row = e >> 4;
                int c = e & 15;
                float v = x[((size_t)(m0 + row) * SS + t) * 16 + c];
                __nv_bfloat16 hi, lo;
                split_bf16(v, hi, lo);
                sh_hi[row * KPAD + c] = hi;
                sh_lo[row * KPAD + c] = lo;
            }
        }
        __syncthreads();

        // ---- fragments ----
        uint32_t ah[2][4];
        uint32_t al[2][4];
#pragma unroll
        for (int mi = 0; mi < 2; mi++) {
            int row = wm * 32 + mi * 16 + lr;
            ldsm_x4(ah[mi][0], ah[mi][1], ah[mi][2], ah[mi][3], &sh_hi[row * KPAD + lkh * 8]);
            ldsm_x4(al[mi][0], al[mi][1], al[mi][2], al[mi][3], &sh_lo[row * KPAD + lkh * 8]);
        }
        uint32_t bh[4][4];
        uint32_t bl[4][4];
#pragma unroll
        for (int g = 0; g < 4; g++) {
            int row = g * 64 + wj * 16 + lr;
            ldsm_x4(bh[g][0], bh[g][1], bh[g][2], bh[g][3], &sw_hi[row * KPAD + lkh * 8]);
            ldsm_x4(bl[g][0], bl[g][1], bl[g][2], bl[g][3], &sw_lo[row * KPAD + lkh * 8]);
        }
        // ---- 48 mma (hi*hi + hi*lo + lo*hi) ----
#pragma unroll
        for (int g = 0; g < 4; g++) {
#pragma unroll
            for (int mi = 0; mi < 2; mi++) {
                mma_bf16(acc[g][mi][0], ah[mi], bh[g][0], bh[g][2]);
                mma_bf16(acc[g][mi][0], ah[mi], bl[g][0], bl[g][2]);
                mma_bf16(acc[g][mi][0], al[mi], bh[g][0], bh[g][2]);
                mma_bf16(acc[g][mi][1], ah[mi], bh[g][1], bh[g][3]);
                mma_bf16(acc[g][mi][1], ah[mi], bl[g][1], bl[g][3]);
                mma_bf16(acc[g][mi][1], al[mi], bh[g][1], bh[g][3]);
            }
        }
        __syncthreads();
    }

    // ---- epilogue: + Zc, LSTM cell, write c and split hraw ----
#pragma unroll
    for (int mi = 0; mi < 2; mi++) {
#pragma unroll
        for (int rh = 0; rh < 2; rh++) {
            int m = m0 + wm * 32 + mi * 16 + gid + rh * 8;
#pragma unroll
            for (int ni = 0; ni < 2; ni++) {
                int jl = wj * 16 + ni * 8 + 2 * tig;
                int jg = j0 + jl;                       // 0..1023
                float pre[4][2];
#pragma unroll
                for (int g = 0; g < 4; g++) {
                    float2 zc = *(const float2*)&g_Zc[(size_t)m * G4 + (g << 10) + jg];
                    pre[g][0] = acc[g][mi][ni][2 * rh + 0] + zc.x;
                    pre[g][1] = acc[g][mi][ni][2 * rh + 1] + zc.y;
                }
                size_t cidx = (size_t)m * DD + jg;
                float2 cold = *(float2*)&g_c[cidx];
                float cn0 = sigf(pre[1][0]) * cold.x + sigf(pre[0][0]) * tanh_f(pre[2][0]);
                float cn1 = sigf(pre[1][1]) * cold.y + sigf(pre[0][1]) * tanh_f(pre[2][1]);
                float2 cnew;
                cnew.x = cn0;
                cnew.y = cn1;
                *(float2*)&g_c[cidx] = cnew;
                float hr0 = sigf(pre[3][0]) * tanh_f(cn0);
                float hr1 = sigf(pre[3][1]) * tanh_f(cn1);
                __nv_bfloat16 h0, l0, h1, l1;
                split_bf16(hr0, h0, l0);
                split_bf16(hr1, h1, l1);
                __nv_bfloat162 ph;
                ph.x = h0;
                ph.y = h1;
                __nv_bfloat162 pl;
                pl.x = l0;
                pl.y = l1;
                *(__nv_bfloat162*)&g_hraw_hi[cidx] = ph;
                *(__nv_bfloat162*)&g_hraw_lo[cidx] = pl;
            }
        }
    }
}

// ---------------- per-step projection (tensor core, bf16 split) ----------------
// grid (4 rt, 32 mt), 128 threads = 4 warps. Block tile: 16m x 64r, K=1024.
__global__ __launch_bounds__(128) void lstm_proj(int t)
{
    __shared__ __align__(16) __nv_bfloat16 pa_hi[16 * KPAD];
    __shared__ __align__(16) __nv_bfloat16 pa_lo[16 * KPAD];
    __shared__ __align__(16) __nv_bfloat16 pw_hi[64 * KPAD];
    __shared__ __align__(16) __nv_bfloat16 pw_lo[64 * KPAD];

    int rt = blockIdx.x;
    int mt = blockIdx.y;
    int r0 = rt * 64;
    int m0 = mt * 16;
    int tid = threadIdx.x;
    int wid = tid >> 5;
    int lane = tid & 31;
    int gid = lane >> 2;
    int tig = lane & 3;
    int lr = lane & 15;
    int lkh = lane >> 4;

    float acc[2][4];
#pragma unroll
    for (int nt = 0; nt < 2; nt++)
#pragma unroll
        for (int q = 0; q < 4; q++) acc[nt][q] = 0.0f;

    for (int kc = 0; kc < 64; ++kc) {
        // stage W (64 r x 16 k), 1 uint4/thread/version
        const uint4* wh = (const uint4*)(g_Whr_hi + (size_t)(rt * 64 + kc) * 64 * 16);
        const uint4* wl = (const uint4*)(g_Whr_lo + (size_t)(rt * 64 + kc) * 64 * 16);
        {
            int row = tid >> 1;
            int hf = tid & 1;
            *(uint4*)&pw_hi[row * KPAD + hf * 8] = wh[tid];
            *(uint4*)&pw_lo[row * KPAD + hf * 8] = wl[tid];
        }
        // stage A (16 m x 16 k), 1 u32/thread/version
        {
            int row = tid >> 3;
            int cp = tid & 7;
            const uint32_t* srch = (const uint32_t*)(g_hraw_hi + (size_t)(m0 + row) * DD + kc * 16);
            const uint32_t* srcl = (const uint32_t*)(g_hraw_lo + (size_t)(m0 + row) * DD + kc * 16);
            *(uint32_t*)&pa_hi[row * KPAD + cp * 2] = srch[cp];
            *(uint32_t*)&pa_lo[row * KPAD + cp * 2] = srcl[cp];
        }
        __syncthreads();

        uint32_t ah[4];
        uint32_t al[4];
        ldsm_x4(ah[0], ah[1], ah[2], ah[3], &pa_hi[lr * KPAD + lkh * 8]);
        ldsm_x4(al[0], al[1], al[2], al[3], &pa_lo[lr * KPAD + lkh * 8]);
        uint32_t bh[4];
        uint32_t bl[4];
        {
            int row = wid * 16 + lr;
            ldsm_x4(bh[0], bh[1], bh[2], bh[3], &pw_hi[row * KPAD + lkh * 8]);
            ldsm_x4(bl[0], bl[1], bl[2], bl[3], &pw_lo[row * KPAD + lkh * 8]);
        }
        mma_bf16(acc[0], ah, bh[0], bh[2]);
        mma_bf16(acc[0], ah, bl[0], bl[2]);
        mma_bf16(acc[0], al, bh[0], bh[2]);
        mma_bf16(acc[1], ah, bh[1], bh[3]);
        mma_bf16(acc[1], ah, bl[1], bl[3]);
        mma_bf16(acc[1], al, bh[1], bh[3]);
        __syncthreads();
    }

    // epilogue: write fp32 hs + split h for next step
#pragma unroll
    for (int nt = 0; nt < 2; nt++) {
#pragma unroll
        for (int rh = 0; rh < 2; rh++) {
            int m = m0 + gid + rh * 8;
            int r = r0 + wid * 16 + nt * 8 + 2 * tig;
            float v0 = acc[nt][2 * rh + 0];
            float v1 = acc[nt][2 * rh + 1];
            float2 v;
            v.x = v0;
            v.y = v1;
            *(float2*)&g_hs[((size_t)m * SS + t) * PP + r] = v;
            __nv_bfloat16 h0, l0, h1, l1;
            split_bf16(v0, h0, l0);
            split_bf16(v1, h1, l1);
            __nv_bfloat162 ph;
            ph.x = h0;
            ph.y = h1;
            __nv_bfloat162 pl;
            pl.x = l0;
            pl.y = l1;
            *(__nv_bfloat162*)&g_h_hi[(size_t)m * PP + r] = ph;
            *(__nv_bfloat162*)&g_h_lo[(size_t)m * PP + r] = pl;
        }
    }
}

// ---------------- output heads: LN + command logits + coords (warp per row) ----------------
__global__ __launch_bounds__(256) void head_kernel(
    const float* __restrict__ ln_g, const float* __restrict__ ln_b,
    const float* __restrict__ W_oc, const float* __restrict__ b_oc,
    const float* __restrict__ W_ox, const float* __restrict__ b_ox,
    const float* __restrict__ scale_p, float* __restrict__ out)
{
    int gw = (blockIdx.x * 256 + threadIdx.x) >> 5;
    int lane = threadIdx.x & 31;
    if (gw >= BB * SS) return;

    const float* hrow = g_hs + (size_t)gw * PP;
    float v[8];
#pragma unroll
    for (int q = 0; q < 2; q++) {
        float4 f = *reinterpret_cast<const float4*>(hrow + lane * 8 + q * 4);
        v[q * 4 + 0] = f.x;
        v[q * 4 + 1] = f.y;
        v[q * 4 + 2] = f.z;
        v[q * 4 + 3] = f.w;
    }
    float s = 0.0f;
    float s2 = 0.0f;
#pragma unroll
    for (int e = 0; e < 8; e++) {
        s += v[e];
        s2 = fmaf(v[e], v[e], s2);
    }
#pragma unroll
    for (int o = 16; o > 0; o >>= 1) {
        s  += __shfl_xor_sync(0xFFFFFFFFu, s, o);
        s2 += __shfl_xor_sync(0xFFFFFFFFu, s2, o);
    }
    float mean = s * (1.0f / 256.0f);
    float var = s2 * (1.0f / 256.0f) - mean * mean;
    float rstd = rsqrtf(var + 1e-5f);

    float hn[8];
#pragma unroll
    for (int e = 0; e < 8; e++) {
        int c = lane * 8 + e;
        hn[e] = (v[e] - mean) * rstd * ln_g[c] + ln_b[c];
    }

    float lgs[10];
#pragma unroll
    for (int cc = 0; cc < 10; cc++) {
        float p = 0.0f;
#pragma unroll
        for (int e = 0; e < 8; e++)
            p = fmaf(hn[e], W_oc[cc * 256 + lane * 8 + e], p);
#pragma unroll
        for (int o = 16; o > 0; o >>= 1) p += __shfl_xor_sync(0xFFFFFFFFu, p, o);
        p += b_oc[cc];
        lgs[cc] = p;
        if (lane == cc) out[(size_t)gw * 10 + cc] = p;
    }

    float csc = *scale_p;
    float* outc = out + (size_t)BB * SS * 10;
#pragma unroll
    for (int q = 0; q < 6; q++) {
        float p = 0.0f;
#pragma unroll
        for (int e = 0; e < 8; e++)
            p = fmaf(hn[e], W_ox[q * 266 + lane * 8 + e], p);
#pragma unroll
        for (int o = 16; o > 0; o >>= 1) p += __shfl_xor_sync(0xFFFFFFFFu, p, o);
#pragma unroll
        for (int cc = 0; cc < 10; cc++)
            p = fmaf(lgs[cc], W_ox[q * 266 + 256 + cc], p);
        p += b_ox[q];
        float z = tanh_f(p * csc);
        if (lane == q) outc[(size_t)gw * 6 + q] = z;
    }
}

// ---------------- launch ----------------
extern "C" void kernel_launch(void* const* d_in, const int* in_sizes, int n_in,
                              void* d_out, int out_size)
{
    const float* x      = (const float*)d_in[0];
    const float* ctx    = (const float*)d_in[1];
    const float* W_cmd  = (const float*)d_in[2];
    const float* b_cmd  = (const float*)d_in[3];
    const float* W_crd  = (const float*)d_in[4];
    const float* b_crd  = (const float*)d_in[5];
    const float* W_ih   = (const float*)d_in[6];
    const float* b_ih   = (const float*)d_in[7];
    const float* W_hh   = (const float*)d_in[8];
    const float* b_hh   = (const float*)d_in[9];
    const float* W_hr   = (const float*)d_in[10];
    const float* ln_g   = (const float*)d_in[11];
    const float* ln_b   = (const float*)d_in[12];
    const float* W_oc   = (const float*)d_in[13];
    const float* b_oc   = (const float*)d_in[14];
    const float* W_ox   = (const float*)d_in[15];
    const float* b_ox   = (const float*)d_in[16];
    const float* cscale = (const float*)d_in[17];
    float* out = (float*)d_out;

    prep_weff<<<G4, 128>>>(W_ih, b_ih, W_cmd, b_cmd, W_crd, b_crd, b_hh);
    prep_zc<<<dim3(G4 / 64, BB / 64), 256>>>(ctx, W_ih);
    prep_whh_split<<<4096, 256>>>(W_hh);
    prep_whr_split<<<1024, 256>>>(W_hr);
    init_state<<<(BB * DD + 255) / 256, 256>>>();

    for (int t = 0; t < SS; t++) {
        lstm_gates<<<dim3(16, 8), 256>>>(x, t);
        lstm_proj<<<dim3(4, 32), 128>>>(t);
    }

    head_kernel<<<(BB * SS * 32 + 255) / 256, 256>>>(
        ln_g, ln_b, W_oc, b_oc, W_ox, b_ox, cscale, out);
}

// round 6
// speedup vs baseline: 2.1083x; 1.5282x over previous
#include <cuda_runtime.h>
#include <cuda_bf16.h>
#include <cstdint>
#include <math.h>

#define BB   512
#define SS   200
#define DD   1024
#define PP   256
#define G4   4096
#define DIN  1280

// ---------------- scratch (device globals; no allocation allowed) ----------------
__device__ float g_bias[G4];                       // folded bias
__device__ float g_Zc[(size_t)BB * G4];            // (512,4096) context+bias
__device__ float g_c[(size_t)BB * DD];             // cell state fp32
__device__ float g_hs[(size_t)BB * SS * PP];       // all projected hiddens (heads)

// fragment-packed weights: [frag = ((jt*17+it)*4+wj)*4+g][lane 32][reg 4] uint32
__device__ __align__(16) uint32_t g_Wpk_hi[16 * 17 * 4 * 4 * 128];
__device__ __align__(16) uint32_t g_Wpk_lo[16 * 17 * 4 * 4 * 128];
// proj weights: [((rt*4+wr)*64+kc)][lane 32][reg 2] uint32
__device__ __align__(16) uint32_t g_Whrpk_hi[8 * 4 * 64 * 64];
__device__ __align__(16) uint32_t g_Whrpk_lo[8 * 4 * 64 * 64];
// pair-packed activations: h [m][kc16][q8], hraw [m][kc64][q8], x [t][m][q8]
__device__ __align__(16) uint32_t g_hpk_hi[(size_t)BB * 16 * 8];
__device__ __align__(16) uint32_t g_hpk_lo[(size_t)BB * 16 * 8];
__device__ __align__(16) uint32_t g_hrawpk_hi[(size_t)BB * 64 * 8];
__device__ __align__(16) uint32_t g_hrawpk_lo[(size_t)BB * 64 * 8];
__device__ __align__(16) uint32_t g_xpk_hi[(size_t)SS * BB * 8];
__device__ __align__(16) uint32_t g_xpk_lo[(size_t)SS * BB * 8];

// ---------------- helpers ----------------
__device__ __forceinline__ float sigf(float x) { return 1.0f / (1.0f + __expf(-x)); }
__device__ __forceinline__ float tanh_f(float x) {
    float e = __expf(-2.0f * fabsf(x));
    float t = (1.0f - e) / (1.0f + e);
    return copysignf(t, x);
}
__device__ __forceinline__ void split_bf16(float x, __nv_bfloat16& hi, __nv_bfloat16& lo) {
    hi = __float2bfloat16(x);
    lo = __float2bfloat16(x - __bfloat162float(hi));
}
// pack (e0,e1) -> hi uint32 (bf16x2, e0 low), lo uint32
__device__ __forceinline__ void split_pack(float e0, float e1, uint32_t& hi, uint32_t& lo) {
    __nv_bfloat16 h0, l0, h1, l1;
    split_bf16(e0, h0, l0);
    split_bf16(e1, h1, l1);
    hi = (uint32_t)__bfloat16_as_ushort(h0) | ((uint32_t)__bfloat16_as_ushort(h1) << 16);
    lo = (uint32_t)__bfloat16_as_ushort(l0) | ((uint32_t)__bfloat16_as_ushort(l1) << 16);
}
__device__ __forceinline__ void mma_bf16(float* d, const uint32_t* a, uint32_t b0, uint32_t b1) {
    asm volatile("mma.sync.aligned.m16n8k16.row.col.f32.bf16.bf16.f32 "
                 "{%0,%1,%2,%3}, {%4,%5,%6,%7}, {%8,%9}, {%0,%1,%2,%3};"
                 : "+f"(d[0]), "+f"(d[1]), "+f"(d[2]), "+f"(d[3])
                 : "r"(a[0]), "r"(a[1]), "r"(a[2]), "r"(a[3]), "r"(b0), "r"(b1));
}

// ---------------- prologue 1: W_eff reduction -> fragment-packed (it=16), bias ----------------
__global__ __launch_bounds__(128) void prep_weff(
    const float* __restrict__ W_ih, const float* __restrict__ b_ih,
    const float* __restrict__ W_cmd, const float* __restrict__ b_cmd,
    const float* __restrict__ W_crd, const float* __restrict__ b_crd,
    const float* __restrict__ b_hh)
{
    int j = blockIdx.x;            // 0..4095 (gate-major row of W_ih)
    int t = threadIdx.x;
    __shared__ float red[17][128];

    float acc[17];
#pragma unroll
    for (int c = 0; c < 17; c++) acc[c] = 0.0f;

    const float* wrow = W_ih + (size_t)j * DIN;
    for (int k = t; k < DD; k += 128) {
        float w = wrow[k];
#pragma unroll
        for (int c = 0; c < 10; c++) acc[c]      = fmaf(w, W_cmd[k * 10 + c], acc[c]);
#pragma unroll
        for (int c = 0; c < 6; c++)  acc[10 + c] = fmaf(w, W_crd[k * 6 + c], acc[10 + c]);
        acc[16] = fmaf(w, b_cmd[k] + b_crd[k], acc[16]);
    }
#pragma unroll
    for (int c = 0; c < 17; c++) red[c][t] = acc[c];
    __syncthreads();
    for (int off = 64; off > 0; off >>= 1) {
        if (t < off) {
#pragma unroll
            for (int c = 0; c < 17; c++) red[c][t] += red[c][t + off];
        }
        __syncthreads();
    }
    if (t == 0) {
        int g    = j >> 10;
        int j_in = j & 1023;
        int jt   = j_in >> 6;
        int rem  = j_in & 63;
        int wj   = rem >> 4;
        int rem2 = rem & 15;
        int ni   = rem2 >> 3;
        int lrow = rem2 & 7;
        size_t fb = (size_t)(((jt * 17 + 16) * 4 + wj) * 4 + g) * 128;
#pragma unroll
        for (int m4 = 0; m4 < 4; m4++) {
#pragma unroll
            for (int bh = 0; bh < 2; bh++) {
                uint32_t hi, lo;
                split_pack(red[2 * m4 + 8 * bh][0], red[2 * m4 + 8 * bh + 1][0], hi, lo);
                size_t idx = fb + (size_t)(lrow * 4 + m4) * 4 + ni * 2 + bh;
                g_Wpk_hi[idx] = hi;
                g_Wpk_lo[idx] = lo;
            }
        }
        g_bias[j] = red[16][0] + b_ih[j] + b_hh[j];
    }
}

// ---------------- prologue 2: Zc = ctx @ W_ih[:,1024:]^T + bias ----------------
__global__ __launch_bounds__(256) void prep_zc(
    const float* __restrict__ ctx, const float* __restrict__ W_ih)
{
    __shared__ float sA[64][17];
    __shared__ float sB[64][17];
    int n0 = blockIdx.x * 64;
    int m0 = blockIdx.y * 64;
    int tid = threadIdx.x;
    int tx = tid & 15;
    int ty = tid >> 4;

    float acc[4][4];
#pragma unroll
    for (int i = 0; i < 4; i++)
#pragma unroll
        for (int j = 0; j < 4; j++) acc[i][j] = 0.0f;

    for (int k0 = 0; k0 < 256; k0 += 16) {
        __syncthreads();
#pragma unroll
        for (int q = 0; q < 4; q++) {
            int e = q * 256 + tid;
            int r = e >> 4;
            int c = e & 15;
            sA[r][c] = ctx[(size_t)(m0 + r) * 256 + k0 + c];
            sB[r][c] = W_ih[(size_t)(n0 + r) * DIN + 1024 + k0 + c];
        }
        __syncthreads();
#pragma unroll
        for (int kk = 0; kk < 16; kk++) {
            float a[4];
            float b[4];
#pragma unroll
            for (int i = 0; i < 4; i++) a[i] = sA[ty + 16 * i][kk];
#pragma unroll
            for (int j = 0; j < 4; j++) b[j] = sB[tx + 16 * j][kk];
#pragma unroll
            for (int i = 0; i < 4; i++)
#pragma unroll
                for (int j = 0; j < 4; j++) acc[i][j] = fmaf(a[i], b[j], acc[i][j]);
        }
    }
#pragma unroll
    for (int i = 0; i < 4; i++) {
        int m = m0 + ty + 16 * i;
#pragma unroll
        for (int j = 0; j < 4; j++) {
            int n = n0 + tx + 16 * j;
            g_Zc[(size_t)m * G4 + n] = acc[i][j] + g_bias[n];
        }
    }
}

// ---------------- prologue 3: fragment-pack W_hh (it 0..15) ----------------
__global__ __launch_bounds__(256) void pack_whh(const float* __restrict__ W_hh)
{
    int idx = blockIdx.x * 256 + threadIdx.x;   // 0..131071
    int lane = idx & 31;
    int g    = (idx >> 5) & 3;
    int wj   = (idx >> 7) & 3;
    int it   = (idx >> 9) & 15;
    int jt   = idx >> 13;
    uint32_t h4[4], l4v[4];
#pragma unroll
    for (int r = 0; r < 4; r++) {
        int ni = r >> 1;
        int bh = r & 1;
        int n = (g << 10) + jt * 64 + wj * 16 + ni * 8 + (lane >> 2);
        int k = it * 16 + 2 * (lane & 3) + 8 * bh;
        split_pack(W_hh[(size_t)n * 256 + k], W_hh[(size_t)n * 256 + k + 1], h4[r], l4v[r]);
    }
    size_t base = (size_t)(((jt * 17 + it) * 4 + wj) * 4 + g) * 128 + lane * 4;
    *(uint4*)&g_Wpk_hi[base] = make_uint4(h4[0], h4[1], h4[2], h4[3]);
    *(uint4*)&g_Wpk_lo[base] = make_uint4(l4v[0], l4v[1], l4v[2], l4v[3]);
}

// ---------------- prologue 4: fragment-pack W_hr ----------------
__global__ __launch_bounds__(256) void pack_whr(const float* __restrict__ W_hr)
{
    int idx = blockIdx.x * 256 + threadIdx.x;   // 0..65535
    int lane = idx & 31;
    int kc = (idx >> 5) & 63;
    int wr = (idx >> 11) & 3;
    int rt = idx >> 13;
    uint32_t h2[2], l2[2];
#pragma unroll
    for (int bh = 0; bh < 2; bh++) {
        int n = rt * 32 + wr * 8 + (lane >> 2);
        int k = kc * 16 + 2 * (lane & 3) + 8 * bh;
        split_pack(W_hr[(size_t)n * 1024 + k], W_hr[(size_t)n * 1024 + k + 1], h2[bh], l2[bh]);
    }
    size_t base = (size_t)((rt * 4 + wr) * 64 + kc) * 64 + lane * 2;
    *(uint2*)&g_Whrpk_hi[base] = make_uint2(h2[0], h2[1]);
    *(uint2*)&g_Whrpk_lo[base] = make_uint2(l2[0], l2[1]);
}

// ---------------- prologue 5: pair-pack x (all 200 steps) ----------------
__global__ __launch_bounds__(256) void pack_x(const float* __restrict__ x)
{
    int idx = blockIdx.x * 256 + threadIdx.x;   // 0..102399
    int m = idx & 511;
    int t = idx >> 9;
    const float* xr = x + ((size_t)m * SS + t) * 16;
    size_t base = ((size_t)t * 512 + m) * 8;
#pragma unroll
    for (int p = 0; p < 8; p++) {
        int q = (p < 4) ? 2 * p : 2 * (p - 4) + 1;
        uint32_t hi, lo;
        split_pack(xr[2 * p], xr[2 * p + 1], hi, lo);
        g_xpk_hi[base + q] = hi;
        g_xpk_lo[base + q] = lo;
    }
}

// ---------------- init state (re-run every launch: determinism) ----------------
__global__ void init_state()
{
    int i = blockIdx.x * blockDim.x + threadIdx.x;
    if (i < BB * DD) g_c[i] = 0.0f;
    if (i < BB * 16 * 8) {
        g_hpk_hi[i] = 0u;
        g_hpk_lo[i] = 0u;
    }
}

// ---------------- gates: fragment loads, no smem, no barriers ----------------
__device__ __forceinline__ void g_loadA(uint2 aH[2][2], uint2 aL[2][2],
                                        int it, int t, int m0, int wm, int l4, int lq)
{
#pragma unroll
    for (int mi = 0; mi < 2; mi++) {
#pragma unroll
        for (int h = 0; h < 2; h++) {
            int row = m0 + wm * 32 + mi * 16 + h * 8 + l4;
            size_t off;
            const uint32_t* ph;
            const uint32_t* pl;
            if (it < 16) {
                off = ((size_t)row * 16 + it) * 8 + lq * 2;
                ph = g_hpk_hi + off;
                pl = g_hpk_lo + off;
            } else {
                off = ((size_t)t * 512 + row) * 8 + lq * 2;
                ph = g_xpk_hi + off;
                pl = g_xpk_lo + off;
            }
            aH[mi][h] = *(const uint2*)ph;
            aL[mi][h] = *(const uint2*)pl;
        }
    }
}
__device__ __forceinline__ void g_loadB(uint4 bH[4], uint4 bL[4], int jt, int it, int wj, int lane)
{
#pragma unroll
    for (int g = 0; g < 4; g++) {
        size_t base = (size_t)(((jt * 17 + it) * 4 + wj) * 4 + g) * 128 + lane * 4;
        bH[g] = *(const uint4*)&g_Wpk_hi[base];
        bL[g] = *(const uint4*)&g_Wpk_lo[base];
    }
}
__device__ __forceinline__ void g_mma(float acc[4][2][2][4],
                                      uint2 aH[2][2], uint2 aL[2][2],
                                      uint4 bH[4], uint4 bL[4])
{
#pragma unroll
    for (int mi = 0; mi < 2; mi++) {
        uint32_t AH[4] = { aH[mi][0].x, aH[mi][1].x, aH[mi][0].y, aH[mi][1].y };
        uint32_t AL[4] = { aL[mi][0].x, aL[mi][1].x, aL[mi][0].y, aL[mi][1].y };
#pragma unroll
        for (int g = 0; g < 4; g++) {
            mma_bf16(acc[g][mi][0], AH, bH[g].x, bH[g].y);
            mma_bf16(acc[g][mi][0], AH, bL[g].x, bL[g].y);
            mma_bf16(acc[g][mi][0], AL, bH[g].x, bH[g].y);
            mma_bf16(acc[g][mi][1], AH, bH[g].z, bH[g].w);
            mma_bf16(acc[g][mi][1], AH, bL[g].z, bL[g].w);
            mma_bf16(acc[g][mi][1], AL, bH[g].z, bH[g].w);
        }
    }
}

__global__ __launch_bounds__(256) void lstm_gates(int t)
{
    int jt = blockIdx.x;
    int mt = blockIdx.y;
    int m0 = mt * 64;
    int j0 = jt * 64;
    int tid = threadIdx.x;
    int wid = tid >> 5;
    int lane = tid & 31;
    int wm = wid >> 2;
    int wj = wid & 3;
    int l4 = lane >> 2;
    int lq = lane & 3;

    float acc[4][2][2][4];
#pragma unroll
    for (int g = 0; g < 4; g++)
#pragma unroll
        for (int mi = 0; mi < 2; mi++)
#pragma unroll
            for (int ni = 0; ni < 2; ni++)
#pragma unroll
                for (int q = 0; q < 4; q++) acc[g][mi][ni][q] = 0.0f;

    uint2 aH0[2][2], aL0[2][2];
    uint4 bH0[4], bL0[4];
    uint2 aH1[2][2], aL1[2][2];
    uint4 bH1[4], bL1[4];

    g_loadA(aH0, aL0, 0, t, m0, wm, l4, lq);
    g_loadB(bH0, bL0, jt, 0, wj, lane);
#pragma unroll
    for (int it = 0; it < 17; it += 2) {
        if (it + 1 < 17) {
            g_loadA(aH1, aL1, it + 1, t, m0, wm, l4, lq);
            g_loadB(bH1, bL1, jt, it + 1, wj, lane);
        }
        g_mma(acc, aH0, aL0, bH0, bL0);
        if (it + 1 < 17) {
            if (it + 2 < 17) {
                g_loadA(aH0, aL0, it + 2, t, m0, wm, l4, lq);
                g_loadB(bH0, bL0, jt, it + 2, wj, lane);
            }
            g_mma(acc, aH1, aL1, bH1, bL1);
        }
    }

    // epilogue: + Zc, LSTM cell, write c and pair-packed hraw
    int kc = jt * 4 + wj;
#pragma unroll
    for (int mi = 0; mi < 2; mi++) {
#pragma unroll
        for (int rh = 0; rh < 2; rh++) {
            int m = m0 + wm * 32 + mi * 16 + rh * 8 + l4;
            uint32_t pH[2], pL[2];
#pragma unroll
            for (int ni = 0; ni < 2; ni++) {
                int jg = j0 + wj * 16 + ni * 8 + 2 * lq;
                float pre0[4], pre1[4];
#pragma unroll
                for (int g = 0; g < 4; g++) {
                    float2 zc = *(const float2*)&g_Zc[(size_t)m * G4 + (g << 10) + jg];
                    pre0[g] = acc[g][mi][ni][2 * rh + 0] + zc.x;
                    pre1[g] = acc[g][mi][ni][2 * rh + 1] + zc.y;
                }
                size_t cidx = (size_t)m * DD + jg;
                float2 cold = *(float2*)&g_c[cidx];
                float cn0 = sigf(pre0[1]) * cold.x + sigf(pre0[0]) * tanh_f(pre0[2]);
                float cn1 = sigf(pre1[1]) * cold.y + sigf(pre1[0]) * tanh_f(pre1[2]);
                *(float2*)&g_c[cidx] = make_float2(cn0, cn1);
                float hr0 = sigf(pre0[3]) * tanh_f(cn0);
                float hr1 = sigf(pre1[3]) * tanh_f(cn1);
                split_pack(hr0, hr1, pH[ni], pL[ni]);
            }
            size_t hoff = ((size_t)m * 64 + kc) * 8 + 2 * lq;
            *(uint2*)&g_hrawpk_hi[hoff] = make_uint2(pH[0], pH[1]);
            *(uint2*)&g_hrawpk_lo[hoff] = make_uint2(pL[0], pL[1]);
        }
    }
}

// ---------------- projection: fragment loads, no smem, no barriers ----------------
__device__ __forceinline__ void p_loadA(uint2 aH[2], uint2 aL[2], int kc, int mbase, int l4, int lq)
{
#pragma unroll
    for (int h = 0; h < 2; h++) {
        int row = mbase + h * 8 + l4;
        size_t off = ((size_t)row * 64 + kc) * 8 + lq * 2;
        aH[h] = *(const uint2*)&g_hrawpk_hi[off];
        aL[h] = *(const uint2*)&g_hrawpk_lo[off];
    }
}
__device__ __forceinline__ void p_loadB(uint2& bh, uint2& bl, int rt, int wr, int kc, int lane)
{
    size_t base = (size_t)((rt * 4 + wr) * 64 + kc) * 64 + lane * 2;
    bh = *(const uint2*)&g_Whrpk_hi[base];
    bl = *(const uint2*)&g_Whrpk_lo[base];
}
__device__ __forceinline__ void p_mma(float acc[4], uint2 aH[2], uint2 aL[2], uint2 bh, uint2 bl)
{
    uint32_t AH[4] = { aH[0].x, aH[1].x, aH[0].y, aH[1].y };
    uint32_t AL[4] = { aL[0].x, aL[1].x, aL[0].y, aL[1].y };
    mma_bf16(acc, AH, bh.x, bh.y);
    mma_bf16(acc, AH, bl.x, bl.y);
    mma_bf16(acc, AL, bh.x, bh.y);
}

__global__ __launch_bounds__(256) void lstm_proj(int t)
{
    int rt = blockIdx.x;            // 0..7  (32 r each)
    int mt = blockIdx.y;            // 0..15 (32 m each)
    int tid = threadIdx.x;
    int wid = tid >> 5;
    int lane = tid & 31;
    int wm = wid >> 2;
    int wr = wid & 3;
    int l4 = lane >> 2;
    int lq = lane & 3;
    int mbase = mt * 32 + wm * 16;

    float acc[4] = {0.0f, 0.0f, 0.0f, 0.0f};
    uint2 aH0[2], aL0[2], b0h, b0l;
    uint2 aH1[2], aL1[2], b1h, b1l;
    p_loadA(aH0, aL0, 0, mbase, l4, lq);
    p_loadB(b0h, b0l, rt, wr, 0, lane);
#pragma unroll 8
    for (int kc = 0; kc < 64; kc += 2) {
        p_loadA(aH1, aL1, kc + 1, mbase, l4, lq);
        p_loadB(b1h, b1l, rt, wr, kc + 1, lane);
        p_mma(acc, aH0, aL0, b0h, b0l);
        if (kc + 2 < 64) {
            p_loadA(aH0, aL0, kc + 2, mbase, l4, lq);
            p_loadB(b0h, b0l, rt, wr, kc + 2, lane);
        }
        p_mma(acc, aH1, aL1, b1h, b1l);
    }

    // epilogue: fp32 hs + pair-packed h for next step
    int r = rt * 32 + wr * 8 + 2 * lq;
    int kc_h = rt * 2 + (wr >> 1);
    int q = 2 * lq + (wr & 1);
#pragma unroll
    for (int h = 0; h < 2; h++) {
        int m = mbase + h * 8 + l4;
        float v0 = acc[2 * h + 0];
        float v1 = acc[2 * h + 1];
        *(float2*)&g_hs[((size_t)m * SS + t) * PP + r] = make_float2(v0, v1);
        uint32_t hi, lo;
        split_pack(v0, v1, hi, lo);
        g_hpk_hi[((size_t)m * 16 + kc_h) * 8 + q] = hi;
        g_hpk_lo[((size_t)m * 16 + kc_h) * 8 + q] = lo;
    }
}

// ---------------- output heads: LN + command logits + coords (warp per row) ----------------
__global__ __launch_bounds__(256) void head_kernel(
    const float* __restrict__ ln_g, const float* __restrict__ ln_b,
    const float* __restrict__ W_oc, const float* __restrict__ b_oc,
    const float* __restrict__ W_ox, const float* __restrict__ b_ox,
    const float* __restrict__ scale_p, float* __restrict__ out)
{
    int gw = (blockIdx.x * 256 + threadIdx.x) >> 5;
    int lane = threadIdx.x & 31;
    if (gw >= BB * SS) return;

    const float* hrow = g_hs + (size_t)gw * PP;
    float v[8];
#pragma unroll
    for (int q = 0; q < 2; q++) {
        float4 f = *reinterpret_cast<const float4*>(hrow + lane * 8 + q * 4);
        v[q * 4 + 0] = f.x;
        v[q * 4 + 1] = f.y;
        v[q * 4 + 2] = f.z;
        v[q * 4 + 3] = f.w;
    }
    float s = 0.0f;
    float s2 = 0.0f;
#pragma unroll
    for (int e = 0; e < 8; e++) {
        s += v[e];
        s2 = fmaf(v[e], v[e], s2);
    }
#pragma unroll
    for (int o = 16; o > 0; o >>= 1) {
        s  += __shfl_xor_sync(0xFFFFFFFFu, s, o);
        s2 += __shfl_xor_sync(0xFFFFFFFFu, s2, o);
    }
    float mean = s * (1.0f / 256.0f);
    float var = s2 * (1.0f / 256.0f) - mean * mean;
    float rstd = rsqrtf(var + 1e-5f);

    float hn[8];
#pragma unroll
    for (int e = 0; e < 8; e++) {
        int c = lane * 8 + e;
        hn[e] = (v[e] - mean) * rstd * ln_g[c] + ln_b[c];
    }

    float lgs[10];
#pragma unroll
    for (int cc = 0; cc < 10; cc++) {
        float p = 0.0f;
#pragma unroll
        for (int e = 0; e < 8; e++)
            p = fmaf(hn[e], W_oc[cc * 256 + lane * 8 + e], p);
#pragma unroll
        for (int o = 16; o > 0; o >>= 1) p += __shfl_xor_sync(0xFFFFFFFFu, p, o);
        p += b_oc[cc];
        lgs[cc] = p;
        if (lane == cc) out[(size_t)gw * 10 + cc] = p;
    }

    float csc = *scale_p;
    float* outc = out + (size_t)BB * SS * 10;
#pragma unroll
    for (int q = 0; q < 6; q++) {
        float p = 0.0f;
#pragma unroll
        for (int e = 0; e < 8; e++)
            p = fmaf(hn[e], W_ox[q * 266 + lane * 8 + e], p);
#pragma unroll
        for (int o = 16; o > 0; o >>= 1) p += __shfl_xor_sync(0xFFFFFFFFu, p, o);
#pragma unroll
        for (int cc = 0; cc < 10; cc++)
            p = fmaf(lgs[cc], W_ox[q * 266 + 256 + cc], p);
        p += b_ox[q];
        float z = tanh_f(p * csc);
        if (lane == q) outc[(size_t)gw * 6 + q] = z;
    }
}

// ---------------- launch ----------------
extern "C" void kernel_launch(void* const* d_in, const int* in_sizes, int n_in,
                              void* d_out, int out_size)
{
    const float* x      = (const float*)d_in[0];
    const float* ctx    = (const float*)d_in[1];
    const float* W_cmd  = (const float*)d_in[2];
    const float* b_cmd  = (const float*)d_in[3];
    const float* W_crd  = (const float*)d_in[4];
    const float* b_crd  = (const float*)d_in[5];
    const float* W_ih   = (const float*)d_in[6];
    const float* b_ih   = (const float*)d_in[7];
    const float* W_hh   = (const float*)d_in[8];
    const float* b_hh   = (const float*)d_in[9];
    const float* W_hr   = (const float*)d_in[10];
    const float* ln_g   = (const float*)d_in[11];
    const float* ln_b   = (const float*)d_in[12];
    const float* W_oc   = (const float*)d_in[13];
    const float* b_oc   = (const float*)d_in[14];
    const float* W_ox   = (const float*)d_in[15];
    const float* b_ox   = (const float*)d_in[16];
    const float* cscale = (const float*)d_in[17];
    float* out = (float*)d_out;

    prep_weff<<<G4, 128>>>(W_ih, b_ih, W_cmd, b_cmd, W_crd, b_crd, b_hh);
    prep_zc<<<dim3(G4 / 64, BB / 64), 256>>>(ctx, W_ih);
    pack_whh<<<512, 256>>>(W_hh);
    pack_whr<<<256, 256>>>(W_hr);
    pack_x<<<400, 256>>>(x);
    init_state<<<(BB * DD + 255) / 256, 256>>>();

    for (int t = 0; t < SS; t++) {
        lstm_gates<<<dim3(16, 8), 256>>>(t);
        lstm_proj<<<dim3(8, 16), 256>>>(t);
    }

    head_kernel<<<(BB * SS * 32 + 255) / 256, 256>>>(
        ln_g, ln_b, W_oc, b_oc, W_ox, b_ox, cscale, out);
}

// round 7
// speedup vs baseline: 2.2485x; 1.0665x over previous
#include <cuda_runtime.h>
#include <cuda_bf16.h>
#include <cstdint>
#include <math.h>

#define BB   512
#define SS   200
#define DD   1024
#define PP   256
#define G4   4096
#define DIN  1280
#define NCTA 128

// ---------------- scratch (device globals; no allocation allowed) ----------------
__device__ float g_bias[G4];                       // folded bias
__device__ float g_Zc[(size_t)BB * G4];            // (512,4096) context+bias
__device__ float g_hs[(size_t)BB * SS * PP];       // all projected hiddens (heads)
__device__ unsigned int g_bar_count;               // grid barrier (cumulative)

// fragment-packed weights: [frag = ((jt*17+it)*4+wj)*4+g][lane 32][reg 4] uint32
__device__ __align__(16) uint32_t g_Wpk_hi[16 * 17 * 4 * 4 * 128];
__device__ __align__(16) uint32_t g_Wpk_lo[16 * 17 * 4 * 4 * 128];
// proj weights: [((rt*4+wr)*64+kc)][lane 32][reg 2] uint32
__device__ __align__(16) uint32_t g_Whrpk_hi[8 * 4 * 64 * 64];
__device__ __align__(16) uint32_t g_Whrpk_lo[8 * 4 * 64 * 64];
// pair-packed activations: h [m][kc16][q8], hraw [m][kc64][q8], x [t][m][q8]
__device__ __align__(16) uint32_t g_hpk_hi[(size_t)BB * 16 * 8];
__device__ __align__(16) uint32_t g_hpk_lo[(size_t)BB * 16 * 8];
__device__ __align__(16) uint32_t g_hrawpk_hi[(size_t)BB * 64 * 8];
__device__ __align__(16) uint32_t g_hrawpk_lo[(size_t)BB * 64 * 8];
__device__ __align__(16) uint32_t g_xpk_hi[(size_t)SS * BB * 8];
__device__ __align__(16) uint32_t g_xpk_lo[(size_t)SS * BB * 8];

// ---------------- helpers ----------------
__device__ __forceinline__ float sigf(float x) { return 1.0f / (1.0f + __expf(-x)); }
__device__ __forceinline__ float tanh_f(float x) {
    float e = __expf(-2.0f * fabsf(x));
    float t = (1.0f - e) / (1.0f + e);
    return copysignf(t, x);
}
__device__ __forceinline__ void split_bf16(float x, __nv_bfloat16& hi, __nv_bfloat16& lo) {
    hi = __float2bfloat16(x);
    lo = __float2bfloat16(x - __bfloat162float(hi));
}
__device__ __forceinline__ void split_pack(float e0, float e1, uint32_t& hi, uint32_t& lo) {
    __nv_bfloat16 h0, l0, h1, l1;
    split_bf16(e0, h0, l0);
    split_bf16(e1, h1, l1);
    hi = (uint32_t)__bfloat16_as_ushort(h0) | ((uint32_t)__bfloat16_as_ushort(h1) << 16);
    lo = (uint32_t)__bfloat16_as_ushort(l0) | ((uint32_t)__bfloat16_as_ushort(l1) << 16);
}
__device__ __forceinline__ void mma_bf16(float* d, const uint32_t* a, uint32_t b0, uint32_t b1) {
    asm volatile("mma.sync.aligned.m16n8k16.row.col.f32.bf16.bf16.f32 "
                 "{%0,%1,%2,%3}, {%4,%5,%6,%7}, {%8,%9}, {%0,%1,%2,%3};"
                 : "+f"(d[0]), "+f"(d[1]), "+f"(d[2]), "+f"(d[3])
                 : "r"(a[0]), "r"(a[1]), "r"(a[2]), "r"(a[3]), "r"(b0), "r"(b1));
}
// deterministic grid barrier: cumulative counter, target = bar_id * NCTA
__device__ __forceinline__ void grid_bar(unsigned int target) {
    __syncthreads();
    if (threadIdx.x == 0) {
        __threadfence();
        atomicAdd(&g_bar_count, 1u);
        while (atomicAdd(&g_bar_count, 0u) < target) { }
        __threadfence();
    }
    __syncthreads();
}

// ---------------- prologue 1: W_eff reduction -> fragment-packed (it=16), bias ----------------
__global__ __launch_bounds__(128) void prep_weff(
    const float* __restrict__ W_ih, const float* __restrict__ b_ih,
    const float* __restrict__ W_cmd, const float* __restrict__ b_cmd,
    const float* __restrict__ W_crd, const float* __restrict__ b_crd,
    const float* __restrict__ b_hh)
{
    int j = blockIdx.x;            // 0..4095 (gate-major row of W_ih)
    int t = threadIdx.x;
    __shared__ float red[17][128];

    float acc[17];
#pragma unroll
    for (int c = 0; c < 17; c++) acc[c] = 0.0f;

    const float* wrow = W_ih + (size_t)j * DIN;
    for (int k = t; k < DD; k += 128) {
        float w = wrow[k];
#pragma unroll
        for (int c = 0; c < 10; c++) acc[c]      = fmaf(w, W_cmd[k * 10 + c], acc[c]);
#pragma unroll
        for (int c = 0; c < 6; c++)  acc[10 + c] = fmaf(w, W_crd[k * 6 + c], acc[10 + c]);
        acc[16] = fmaf(w, b_cmd[k] + b_crd[k], acc[16]);
    }
#pragma unroll
    for (int c = 0; c < 17; c++) red[c][t] = acc[c];
    __syncthreads();
    for (int off = 64; off > 0; off >>= 1) {
        if (t < off) {
#pragma unroll
            for (int c = 0; c < 17; c++) red[c][t] += red[c][t + off];
        }
        __syncthreads();
    }
    if (t == 0) {
        int g    = j >> 10;
        int j_in = j & 1023;
        int jt   = j_in >> 6;
        int rem  = j_in & 63;
        int wj   = rem >> 4;
        int rem2 = rem & 15;
        int ni   = rem2 >> 3;
        int lrow = rem2 & 7;
        size_t fb = (size_t)(((jt * 17 + 16) * 4 + wj) * 4 + g) * 128;
#pragma unroll
        for (int m4 = 0; m4 < 4; m4++) {
#pragma unroll
            for (int bh = 0; bh < 2; bh++) {
                uint32_t hi, lo;
                split_pack(red[2 * m4 + 8 * bh][0], red[2 * m4 + 8 * bh + 1][0], hi, lo);
                size_t idx = fb + (size_t)(lrow * 4 + m4) * 4 + ni * 2 + bh;
                g_Wpk_hi[idx] = hi;
                g_Wpk_lo[idx] = lo;
            }
        }
        g_bias[j] = red[16][0] + b_ih[j] + b_hh[j];
    }
}

// ---------------- prologue 2: Zc = ctx @ W_ih[:,1024:]^T + bias ----------------
__global__ __launch_bounds__(256) void prep_zc(
    const float* __restrict__ ctx, const float* __restrict__ W_ih)
{
    __shared__ float sA[64][17];
    __shared__ float sB[64][17];
    int n0 = blockIdx.x * 64;
    int m0 = blockIdx.y * 64;
    int tid = threadIdx.x;
    int tx = tid & 15;
    int ty = tid >> 4;

    float acc[4][4];
#pragma unroll
    for (int i = 0; i < 4; i++)
#pragma unroll
        for (int j = 0; j < 4; j++) acc[i][j] = 0.0f;

    for (int k0 = 0; k0 < 256; k0 += 16) {
        __syncthreads();
#pragma unroll
        for (int q = 0; q < 4; q++) {
            int e = q * 256 + tid;
            int r = e >> 4;
            int c = e & 15;
            sA[r][c] = ctx[(size_t)(m0 + r) * 256 + k0 + c];
            sB[r][c] = W_ih[(size_t)(n0 + r) * DIN + 1024 + k0 + c];
        }
        __syncthreads();
#pragma unroll
        for (int kk = 0; kk < 16; kk++) {
            float a[4];
            float b[4];
#pragma unroll
            for (int i = 0; i < 4; i++) a[i] = sA[ty + 16 * i][kk];
#pragma unroll
            for (int j = 0; j < 4; j++) b[j] = sB[tx + 16 * j][kk];
#pragma unroll
            for (int i = 0; i < 4; i++)
#pragma unroll
                for (int j = 0; j < 4; j++) acc[i][j] = fmaf(a[i], b[j], acc[i][j]);
        }
    }
#pragma unroll
    for (int i = 0; i < 4; i++) {
        int m = m0 + ty + 16 * i;
#pragma unroll
        for (int j = 0; j < 4; j++) {
            int n = n0 + tx + 16 * j;
            g_Zc[(size_t)m * G4 + n] = acc[i][j] + g_bias[n];
        }
    }
}

// ---------------- prologue 3: fragment-pack W_hh (it 0..15) ----------------
__global__ __launch_bounds__(256) void pack_whh(const float* __restrict__ W_hh)
{
    int idx = blockIdx.x * 256 + threadIdx.x;   // 0..131071
    int lane = idx & 31;
    int g    = (idx >> 5) & 3;
    int wj   = (idx >> 7) & 3;
    int it   = (idx >> 9) & 15;
    int jt   = idx >> 13;
    uint32_t h4[4], l4v[4];
#pragma unroll
    for (int r = 0; r < 4; r++) {
        int ni = r >> 1;
        int bh = r & 1;
        int n = (g << 10) + jt * 64 + wj * 16 + ni * 8 + (lane >> 2);
        int k = it * 16 + 2 * (lane & 3) + 8 * bh;
        split_pack(W_hh[(size_t)n * 256 + k], W_hh[(size_t)n * 256 + k + 1], h4[r], l4v[r]);
    }
    size_t base = (size_t)(((jt * 17 + it) * 4 + wj) * 4 + g) * 128 + lane * 4;
    *(uint4*)&g_Wpk_hi[base] = make_uint4(h4[0], h4[1], h4[2], h4[3]);
    *(uint4*)&g_Wpk_lo[base] = make_uint4(l4v[0], l4v[1], l4v[2], l4v[3]);
}

// ---------------- prologue 4: fragment-pack W_hr ----------------
__global__ __launch_bounds__(256) void pack_whr(const float* __restrict__ W_hr)
{
    int idx = blockIdx.x * 256 + threadIdx.x;   // 0..65535
    int lane = idx & 31;
    int kc = (idx >> 5) & 63;
    int wr = (idx >> 11) & 3;
    int rt = idx >> 13;
    uint32_t h2[2], l2[2];
#pragma unroll
    for (int bh = 0; bh < 2; bh++) {
        int n = rt * 32 + wr * 8 + (lane >> 2);
        int k = kc * 16 + 2 * (lane & 3) + 8 * bh;
        split_pack(W_hr[(size_t)n * 1024 + k], W_hr[(size_t)n * 1024 + k + 1], h2[bh], l2[bh]);
    }
    size_t base = (size_t)((rt * 4 + wr) * 64 + kc) * 64 + lane * 2;
    *(uint2*)&g_Whrpk_hi[base] = make_uint2(h2[0], h2[1]);
    *(uint2*)&g_Whrpk_lo[base] = make_uint2(l2[0], l2[1]);
}

// ---------------- prologue 5: pair-pack x (all 200 steps) ----------------
__global__ __launch_bounds__(256) void pack_x(const float* __restrict__ x)
{
    int idx = blockIdx.x * 256 + threadIdx.x;   // 0..102399
    int m = idx & 511;
    int t = idx >> 9;
    const float* xr = x + ((size_t)m * SS + t) * 16;
    size_t base = ((size_t)t * 512 + m) * 8;
#pragma unroll
    for (int p = 0; p < 8; p++) {
        int q = (p < 4) ? 2 * p : 2 * (p - 4) + 1;
        uint32_t hi, lo;
        split_pack(xr[2 * p], xr[2 * p + 1], hi, lo);
        g_xpk_hi[base + q] = hi;
        g_xpk_lo[base + q] = lo;
    }
}

// ---------------- init (re-run every launch: determinism) ----------------
__global__ void init_state()
{
    int i = blockIdx.x * blockDim.x + threadIdx.x;
    if (i == 0) g_bar_count = 0u;
    if (i < BB * 16 * 8) {
        g_hpk_hi[i] = 0u;
        g_hpk_lo[i] = 0u;
    }
}

// ---------------- persistent-kernel phase helpers ----------------
__device__ __forceinline__ void g_loadA(uint2 aH[2][2], uint2 aL[2][2],
                                        int it, int t, int m0, int wm, int l4, int lq)
{
#pragma unroll
    for (int mi = 0; mi < 2; mi++) {
#pragma unroll
        for (int h = 0; h < 2; h++) {
            int row = m0 + wm * 32 + mi * 16 + h * 8 + l4;
            if (it < 16) {
                size_t off = ((size_t)row * 16 + it) * 8 + lq * 2;
                aH[mi][h] = __ldcg((const uint2*)(g_hpk_hi + off));
                aL[mi][h] = __ldcg((const uint2*)(g_hpk_lo + off));
            } else {
                size_t off = ((size_t)t * 512 + row) * 8 + lq * 2;
                aH[mi][h] = __ldcg((const uint2*)(g_xpk_hi + off));
                aL[mi][h] = __ldcg((const uint2*)(g_xpk_lo + off));
            }
        }
    }
}
__device__ __forceinline__ void g_loadB(uint4 bH[4], uint4 bL[4], int jt, int it, int wj, int lane)
{
#pragma unroll
    for (int g = 0; g < 4; g++) {
        size_t base = (size_t)(((jt * 17 + it) * 4 + wj) * 4 + g) * 128 + lane * 4;
        bH[g] = *(const uint4*)&g_Wpk_hi[base];
        bL[g] = *(const uint4*)&g_Wpk_lo[base];
    }
}
__device__ __forceinline__ void g_mma(float acc[4][2][2][4],
                                      uint2 aH[2][2], uint2 aL[2][2],
                                      uint4 bH[4], uint4 bL[4])
{
#pragma unroll
    for (int mi = 0; mi < 2; mi++) {
        uint32_t AH[4] = { aH[mi][0].x, aH[mi][1].x, aH[mi][0].y, aH[mi][1].y };
        uint32_t AL[4] = { aL[mi][0].x, aL[mi][1].x, aL[mi][0].y, aL[mi][1].y };
#pragma unroll
        for (int g = 0; g < 4; g++) {
            mma_bf16(acc[g][mi][0], AH, bH[g].x, bH[g].y);
            mma_bf16(acc[g][mi][0], AH, bL[g].x, bL[g].y);
            mma_bf16(acc[g][mi][0], AL, bH[g].x, bH[g].y);
            mma_bf16(acc[g][mi][1], AH, bH[g].z, bH[g].w);
            mma_bf16(acc[g][mi][1], AH, bL[g].z, bL[g].w);
            mma_bf16(acc[g][mi][1], AL, bH[g].z, bH[g].w);
        }
    }
}
__device__ __forceinline__ void p_loadA(uint2 aH[2], uint2 aL[2], int kc, int mbase, int l4, int lq)
{
#pragma unroll
    for (int h = 0; h < 2; h++) {
        int row = mbase + h * 8 + l4;
        size_t off = ((size_t)row * 64 + kc) * 8 + lq * 2;
        aH[h] = __ldcg((const uint2*)&g_hrawpk_hi[off]);
        aL[h] = __ldcg((const uint2*)&g_hrawpk_lo[off]);
    }
}
__device__ __forceinline__ void p_loadB(uint2& bh, uint2& bl, int rt, int wr, int kc, int lane)
{
    size_t base = (size_t)((rt * 4 + wr) * 64 + kc) * 64 + lane * 2;
    bh = *(const uint2*)&g_Whrpk_hi[base];
    bl = *(const uint2*)&g_Whrpk_lo[base];
}
__device__ __forceinline__ void p_mma(float acc[4], uint2 aH[2], uint2 aL[2], uint2 bh, uint2 bl)
{
    uint32_t AH[4] = { aH[0].x, aH[1].x, aH[0].y, aH[1].y };
    uint32_t AL[4] = { aL[0].x, aL[1].x, aL[0].y, aL[1].y };
    mma_bf16(acc, AH, bh.x, bh.y);
    mma_bf16(acc, AH, bl.x, bl.y);
    mma_bf16(acc, AL, bh.x, bh.y);
}

// ---------------- persistent recurrence: 200 steps, 2 grid barriers/step ----------------
// smem: Zc tile 64*256 f32 (64KB) + c tile 64*64 f32 (16KB)
__global__ __launch_bounds__(256, 1) void lstm_persistent()
{
    extern __shared__ float smem[];
    float* sZc = smem;            // [ml 64][g*64+jl 256]
    float* sC  = smem + 64 * 256; // [ml 64][jl 64]

    int bid = blockIdx.x;
    // gates tile map
    int jt = bid >> 3;
    int mt = bid & 7;
    int m0 = mt * 64;
    int j0 = jt * 64;
    // proj tile map
    int rt2 = bid & 7;
    int mt2 = bid >> 3;

    int tid = threadIdx.x;
    int wid = tid >> 5;
    int lane = tid & 31;
    int wm = wid >> 2;
    int wj = wid & 3;
    int l4 = lane >> 2;
    int lq = lane & 3;

    // stage Zc tile into smem (once), zero c tile
    for (int idx = tid; idx < 64 * 256; idx += 256) {
        int ml = idx >> 8;
        int col = idx & 255;
        int g = col >> 6;
        int jl = col & 63;
        sZc[idx] = g_Zc[(size_t)(m0 + ml) * G4 + (g << 10) + j0 + jl];
    }
    for (int idx = tid; idx < 64 * 64; idx += 256) sC[idx] = 0.0f;
    __syncthreads();

    unsigned int bar = 0;

    for (int t = 0; t < SS; t++) {
        // ================= gates phase =================
        {
            float acc[4][2][2][4];
#pragma unroll
            for (int g = 0; g < 4; g++)
#pragma unroll
                for (int mi = 0; mi < 2; mi++)
#pragma unroll
                    for (int ni = 0; ni < 2; ni++)
#pragma unroll
                        for (int q = 0; q < 4; q++) acc[g][mi][ni][q] = 0.0f;

            uint2 aH0[2][2], aL0[2][2];
            uint4 bH0[4], bL0[4];
            uint2 aH1[2][2], aL1[2][2];
            uint4 bH1[4], bL1[4];

            g_loadA(aH0, aL0, 0, t, m0, wm, l4, lq);
            g_loadB(bH0, bL0, jt, 0, wj, lane);
#pragma unroll
            for (int it = 0; it < 17; it += 2) {
                if (it + 1 < 17) {
                    g_loadA(aH1, aL1, it + 1, t, m0, wm, l4, lq);
                    g_loadB(bH1, bL1, jt, it + 1, wj, lane);
                }
                g_mma(acc, aH0, aL0, bH0, bL0);
                if (it + 1 < 17) {
                    if (it + 2 < 17) {
                        g_loadA(aH0, aL0, it + 2, t, m0, wm, l4, lq);
                        g_loadB(bH0, bL0, jt, it + 2, wj, lane);
                    }
                    g_mma(acc, aH1, aL1, bH1, bL1);
                }
            }

            // epilogue: + Zc(smem), LSTM cell (c in smem), write pair-packed hraw
            int kc = jt * 4 + wj;
#pragma unroll
            for (int mi = 0; mi < 2; mi++) {
#pragma unroll
                for (int rh = 0; rh < 2; rh++) {
                    int ml = wm * 32 + mi * 16 + rh * 8 + l4;
                    int m = m0 + ml;
                    uint32_t pH[2], pL[2];
#pragma unroll
                    for (int ni = 0; ni < 2; ni++) {
                        int jl = wj * 16 + ni * 8 + 2 * lq;
                        float pre0[4], pre1[4];
#pragma unroll
                        for (int g = 0; g < 4; g++) {
                            float2 zc = *(const float2*)&sZc[ml * 256 + g * 64 + jl];
                            pre0[g] = acc[g][mi][ni][2 * rh + 0] + zc.x;
                            pre1[g] = acc[g][mi][ni][2 * rh + 1] + zc.y;
                        }
                        float2 cold = *(float2*)&sC[ml * 64 + jl];
                        float cn0 = sigf(pre0[1]) * cold.x + sigf(pre0[0]) * tanh_f(pre0[2]);
                        float cn1 = sigf(pre1[1]) * cold.y + sigf(pre1[0]) * tanh_f(pre1[2]);
                        *(float2*)&sC[ml * 64 + jl] = make_float2(cn0, cn1);
                        float hr0 = sigf(pre0[3]) * tanh_f(cn0);
                        float hr1 = sigf(pre1[3]) * tanh_f(cn1);
                        split_pack(hr0, hr1, pH[ni], pL[ni]);
                    }
                    size_t hoff = ((size_t)m * 64 + kc) * 8 + 2 * lq;
                    *(uint2*)&g_hrawpk_hi[hoff] = make_uint2(pH[0], pH[1]);
                    *(uint2*)&g_hrawpk_lo[hoff] = make_uint2(pL[0], pL[1]);
                }
            }
        }
        grid_bar(++bar * NCTA);

        // ================= projection phase =================
        {
            int wr = wj;
            int mbase = mt2 * 32 + wm * 16;

            float acc[4] = {0.0f, 0.0f, 0.0f, 0.0f};
            uint2 aH0[2], aL0[2], b0h, b0l;
            uint2 aH1[2], aL1[2], b1h, b1l;
            p_loadA(aH0, aL0, 0, mbase, l4, lq);
            p_loadB(b0h, b0l, rt2, wr, 0, lane);
#pragma unroll 8
            for (int kc = 0; kc < 64; kc += 2) {
                p_loadA(aH1, aL1, kc + 1, mbase, l4, lq);
                p_loadB(b1h, b1l, rt2, wr, kc + 1, lane);
                p_mma(acc, aH0, aL0, b0h, b0l);
                if (kc + 2 < 64) {
                    p_loadA(aH0, aL0, kc + 2, mbase, l4, lq);
                    p_loadB(b0h, b0l, rt2, wr, kc + 2, lane);
                }
                p_mma(acc, aH1, aL1, b1h, b1l);
            }

            int r = rt2 * 32 + wr * 8 + 2 * lq;
            int kc_h = rt2 * 2 + (wr >> 1);
            int q = 2 * lq + (wr & 1);
#pragma unroll
            for (int h = 0; h < 2; h++) {
                int m = mbase + h * 8 + l4;
                float v0 = acc[2 * h + 0];
                float v1 = acc[2 * h + 1];
                *(float2*)&g_hs[((size_t)m * SS + t) * PP + r] = make_float2(v0, v1);
                uint32_t hi, lo;
                split_pack(v0, v1, hi, lo);
                g_hpk_hi[((size_t)m * 16 + kc_h) * 8 + q] = hi;
                g_hpk_lo[((size_t)m * 16 + kc_h) * 8 + q] = lo;
            }
        }
        grid_bar(++bar * NCTA);
    }
}

// ---------------- output heads: LN + command logits + coords (warp per row) ----------------
__global__ __launch_bounds__(256) void head_kernel(
    const float* __restrict__ ln_g, const float* __restrict__ ln_b,
    const float* __restrict__ W_oc, const float* __restrict__ b_oc,
    const float* __restrict__ W_ox, const float* __restrict__ b_ox,
    const float* __restrict__ scale_p, float* __restrict__ out)
{
    int gw = (blockIdx.x * 256 + threadIdx.x) >> 5;
    int lane = threadIdx.x & 31;
    if (gw >= BB * SS) return;

    const float* hrow = g_hs + (size_t)gw * PP;
    float v[8];
#pragma unroll
    for (int q = 0; q < 2; q++) {
        float4 f = *reinterpret_cast<const float4*>(hrow + lane * 8 + q * 4);
        v[q * 4 + 0] = f.x;
        v[q * 4 + 1] = f.y;
        v[q * 4 + 2] = f.z;
        v[q * 4 + 3] = f.w;
    }
    float s = 0.0f;
    float s2 = 0.0f;
#pragma unroll
    for (int e = 0; e < 8; e++) {
        s += v[e];
        s2 = fmaf(v[e], v[e], s2);
    }
#pragma unroll
    for (int o = 16; o > 0; o >>= 1) {
        s  += __shfl_xor_sync(0xFFFFFFFFu, s, o);
        s2 += __shfl_xor_sync(0xFFFFFFFFu, s2, o);
    }
    float mean = s * (1.0f / 256.0f);
    float var = s2 * (1.0f / 256.0f) - mean * mean;
    float rstd = rsqrtf(var + 1e-5f);

    float hn[8];
#pragma unroll
    for (int e = 0; e < 8; e++) {
        int c = lane * 8 + e;
        hn[e] = (v[e] - mean) * rstd * ln_g[c] + ln_b[c];
    }

    float lgs[10];
#pragma unroll
    for (int cc = 0; cc < 10; cc++) {
        float p = 0.0f;
#pragma unroll
        for (int e = 0; e < 8; e++)
            p = fmaf(hn[e], W_oc[cc * 256 + lane * 8 + e], p);
#pragma unroll
        for (int o = 16; o > 0; o >>= 1) p += __shfl_xor_sync(0xFFFFFFFFu, p, o);
        p += b_oc[cc];
        lgs[cc] = p;
        if (lane == cc) out[(size_t)gw * 10 + cc] = p;
    }

    float csc = *scale_p;
    float* outc = out + (size_t)BB * SS * 10;
#pragma unroll
    for (int q = 0; q < 6; q++) {
        float p = 0.0f;
#pragma unroll
        for (int e = 0; e < 8; e++)
            p = fmaf(hn[e], W_ox[q * 266 + lane * 8 + e], p);
#pragma unroll
        for (int o = 16; o > 0; o >>= 1) p += __shfl_xor_sync(0xFFFFFFFFu, p, o);
#pragma unroll
        for (int cc = 0; cc < 10; cc++)
            p = fmaf(lgs[cc], W_ox[q * 266 + 256 + cc], p);
        p += b_ox[q];
        float z = tanh_f(p * csc);
        if (lane == q) outc[(size_t)gw * 6 + q] = z;
    }
}

// ---------------- launch ----------------
extern "C" void kernel_launch(void* const* d_in, const int* in_sizes, int n_in,
                              void* d_out, int out_size)
{
    const float* x      = (const float*)d_in[0];
    const float* ctx    = (const float*)d_in[1];
    const float* W_cmd  = (const float*)d_in[2];
    const float* b_cmd  = (const float*)d_in[3];
    const float* W_crd  = (const float*)d_in[4];
    const float* b_crd  = (const float*)d_in[5];
    const float* W_ih   = (const float*)d_in[6];
    const float* b_ih   = (const float*)d_in[7];
    const float* W_hh   = (const float*)d_in[8];
    const float* b_hh   = (const float*)d_in[9];
    const float* W_hr   = (const float*)d_in[10];
    const float* ln_g   = (const float*)d_in[11];
    const float* ln_b   = (const float*)d_in[12];
    const float* W_oc   = (const float*)d_in[13];
    const float* b_oc   = (const float*)d_in[14];
    const float* W_ox   = (const float*)d_in[15];
    const float* b_ox   = (const float*)d_in[16];
    const float* cscale = (const float*)d_in[17];
    float* out = (float*)d_out;

    static bool attr_set = false;
    if (!attr_set) {
        cudaFuncSetAttribute(lstm_persistent,
                             cudaFuncAttributeMaxDynamicSharedMemorySize,
                             (64 * 256 + 64 * 64) * (int)sizeof(float));
        attr_set = true;
    }

    prep_weff<<<G4, 128>>>(W_ih, b_ih, W_cmd, b_cmd, W_crd, b_crd, b_hh);
    prep_zc<<<dim3(G4 / 64, BB / 64), 256>>>(ctx, W_ih);
    pack_whh<<<512, 256>>>(W_hh);
    pack_whr<<<256, 256>>>(W_hr);
    pack_x<<<400, 256>>>(x);
    init_state<<<(BB * 16 * 8 + 255) / 256, 256>>>();

    lstm_persistent<<<NCTA, 256, (64 * 256 + 64 * 64) * sizeof(float)>>>();

    head_kernel<<<(BB * SS * 32 + 255) / 256, 256>>>(
        ln_g, ln_b, W_oc, b_oc, W_ox, b_ox, cscale, out);
}

// round 8
// speedup vs baseline: 2.2969x; 1.0215x over previous
#include <cuda_runtime.h>
#include <cuda_bf16.h>
#include <cstdint>
#include <math.h>

#define BB   512
#define SS   200
#define DD   1024
#define PP   256
#define G4   4096
#define DIN  1280
#define NCTA 128

// ---------------- scratch (device globals; no allocation allowed) ----------------
__device__ float g_bias[G4];                       // folded bias
__device__ float g_Zc[(size_t)BB * G4];            // (512,4096) context+bias
__device__ float g_hs[(size_t)BB * SS * PP];       // all projected hiddens (heads)
__device__ unsigned int g_bar_count;               // grid barrier (cumulative)

// gates weights, fragment-packed for L1 residency:
// uint4 index b4 = (((ct*17+it)*4+g)*2+jp)*32 + lane ; .x/.y = nj=2jp (klo,khi), .z/.w = nj=2jp+1
__device__ __align__(16) uint32_t g_Wpk_hi[32 * 17 * 4 * 2 * 32 * 4];
__device__ __align__(16) uint32_t g_Wpk_lo[32 * 17 * 4 * 2 * 32 * 4];
// proj weights: [((rt*4+wr)*64+kc)][lane 32][reg 2] uint32
__device__ __align__(16) uint32_t g_Whrpk_hi[8 * 4 * 64 * 64];
__device__ __align__(16) uint32_t g_Whrpk_lo[8 * 4 * 64 * 64];
// pair-packed activations: h [m][kc16][q8], hraw [m][kc64][q8], x [t][m][q8]
__device__ __align__(16) uint32_t g_hpk_hi[(size_t)BB * 16 * 8];
__device__ __align__(16) uint32_t g_hpk_lo[(size_t)BB * 16 * 8];
__device__ __align__(16) uint32_t g_hrawpk_hi[(size_t)BB * 64 * 8];
__device__ __align__(16) uint32_t g_hrawpk_lo[(size_t)BB * 64 * 8];
__device__ __align__(16) uint32_t g_xpk_hi[(size_t)SS * BB * 8];
__device__ __align__(16) uint32_t g_xpk_lo[(size_t)SS * BB * 8];

// ---------------- helpers ----------------
__device__ __forceinline__ float sigf(float x) { return 1.0f / (1.0f + __expf(-x)); }
__device__ __forceinline__ float tanh_f(float x) {
    float e = __expf(-2.0f * fabsf(x));
    float t = (1.0f - e) / (1.0f + e);
    return copysignf(t, x);
}
__device__ __forceinline__ void split_bf16(float x, __nv_bfloat16& hi, __nv_bfloat16& lo) {
    hi = __float2bfloat16(x);
    lo = __float2bfloat16(x - __bfloat162float(hi));
}
__device__ __forceinline__ void split_pack(float e0, float e1, uint32_t& hi, uint32_t& lo) {
    __nv_bfloat16 h0, l0, h1, l1;
    split_bf16(e0, h0, l0);
    split_bf16(e1, h1, l1);
    hi = (uint32_t)__bfloat16_as_ushort(h0) | ((uint32_t)__bfloat16_as_ushort(h1) << 16);
    lo = (uint32_t)__bfloat16_as_ushort(l0) | ((uint32_t)__bfloat16_as_ushort(l1) << 16);
}
__device__ __forceinline__ void mma_bf16(float* d, const uint32_t* a, uint32_t b0, uint32_t b1) {
    asm volatile("mma.sync.aligned.m16n8k16.row.col.f32.bf16.bf16.f32 "
                 "{%0,%1,%2,%3}, {%4,%5,%6,%7}, {%8,%9}, {%0,%1,%2,%3};"
                 : "+f"(d[0]), "+f"(d[1]), "+f"(d[2]), "+f"(d[3])
                 : "r"(a[0]), "r"(a[1]), "r"(a[2]), "r"(a[3]), "r"(b0), "r"(b1));
}
// deterministic grid barrier: cumulative counter, target = bar_id * NCTA
__device__ __forceinline__ void grid_bar(unsigned int target) {
    __syncthreads();
    if (threadIdx.x == 0) {
        __threadfence();
        atomicAdd(&g_bar_count, 1u);
        while (atomicAdd(&g_bar_count, 0u) < target) { }
        __threadfence();
    }
    __syncthreads();
}

// ---------------- prologue 1: W_eff reduction -> fragment-packed (it=16), bias ----------------
__global__ __launch_bounds__(128) void prep_weff(
    const float* __restrict__ W_ih, const float* __restrict__ b_ih,
    const float* __restrict__ W_cmd, const float* __restrict__ b_cmd,
    const float* __restrict__ W_crd, const float* __restrict__ b_crd,
    const float* __restrict__ b_hh)
{
    int j = blockIdx.x;            // 0..4095 (gate-major row)
    int t = threadIdx.x;
    __shared__ float red[17][128];

    float acc[17];
#pragma unroll
    for (int c = 0; c < 17; c++) acc[c] = 0.0f;

    const float* wrow = W_ih + (size_t)j * DIN;
    for (int k = t; k < DD; k += 128) {
        float w = wrow[k];
#pragma unroll
        for (int c = 0; c < 10; c++) acc[c]      = fmaf(w, W_cmd[k * 10 + c], acc[c]);
#pragma unroll
        for (int c = 0; c < 6; c++)  acc[10 + c] = fmaf(w, W_crd[k * 6 + c], acc[10 + c]);
        acc[16] = fmaf(w, b_cmd[k] + b_crd[k], acc[16]);
    }
#pragma unroll
    for (int c = 0; c < 17; c++) red[c][t] = acc[c];
    __syncthreads();
    for (int off = 64; off > 0; off >>= 1) {
        if (t < off) {
#pragma unroll
            for (int c = 0; c < 17; c++) red[c][t] += red[c][t + off];
        }
        __syncthreads();
    }
    if (t == 0) {
        int g     = j >> 10;
        int jglob = j & 1023;
        int ct    = jglob >> 5;
        int rem   = jglob & 31;
        int nj    = rem >> 3;
        int l4    = rem & 7;
        int jp    = nj >> 1;
        int v     = nj & 1;
#pragma unroll
        for (int lq = 0; lq < 4; lq++) {
#pragma unroll
            for (int kh = 0; kh < 2; kh++) {
                uint32_t hi, lo;
                split_pack(red[2 * lq + 8 * kh][0], red[2 * lq + 8 * kh + 1][0], hi, lo);
                size_t b4 = (size_t)((((ct * 17 + 16) * 4 + g) * 2 + jp) * 32 + (l4 * 4 + lq));
                size_t u = b4 * 4 + v * 2 + kh;
                g_Wpk_hi[u] = hi;
                g_Wpk_lo[u] = lo;
            }
        }
        g_bias[j] = red[16][0] + b_ih[j] + b_hh[j];
    }
}

// ---------------- prologue 2: Zc = ctx @ W_ih[:,1024:]^T + bias ----------------
__global__ __launch_bounds__(256) void prep_zc(
    const float* __restrict__ ctx, const float* __restrict__ W_ih)
{
    __shared__ float sA[64][17];
    __shared__ float sB[64][17];
    int n0 = blockIdx.x * 64;
    int m0 = blockIdx.y * 64;
    int tid = threadIdx.x;
    int tx = tid & 15;
    int ty = tid >> 4;

    float acc[4][4];
#pragma unroll
    for (int i = 0; i < 4; i++)
#pragma unroll
        for (int j = 0; j < 4; j++) acc[i][j] = 0.0f;

    for (int k0 = 0; k0 < 256; k0 += 16) {
        __syncthreads();
#pragma unroll
        for (int q = 0; q < 4; q++) {
            int e = q * 256 + tid;
            int r = e >> 4;
            int c = e & 15;
            sA[r][c] = ctx[(size_t)(m0 + r) * 256 + k0 + c];
            sB[r][c] = W_ih[(size_t)(n0 + r) * DIN + 1024 + k0 + c];
        }
        __syncthreads();
#pragma unroll
        for (int kk = 0; kk < 16; kk++) {
            float a[4];
            float b[4];
#pragma unroll
            for (int i = 0; i < 4; i++) a[i] = sA[ty + 16 * i][kk];
#pragma unroll
            for (int j = 0; j < 4; j++) b[j] = sB[tx + 16 * j][kk];
#pragma unroll
            for (int i = 0; i < 4; i++)
#pragma unroll
                for (int j = 0; j < 4; j++) acc[i][j] = fmaf(a[i], b[j], acc[i][j]);
        }
    }
#pragma unroll
    for (int i = 0; i < 4; i++) {
        int m = m0 + ty + 16 * i;
#pragma unroll
        for (int j = 0; j < 4; j++) {
            int n = n0 + tx + 16 * j;
            g_Zc[(size_t)m * G4 + n] = acc[i][j] + g_bias[n];
        }
    }
}

// ---------------- prologue 3: fragment-pack W_hh (it 0..15) ----------------
__global__ __launch_bounds__(256) void pack_whh(const float* __restrict__ W_hh)
{
    int idx = blockIdx.x * 256 + threadIdx.x;   // 0..131071
    int lane = idx & 31;
    int jp   = (idx >> 5) & 1;
    int g    = (idx >> 6) & 3;
    int it   = (idx >> 8) & 15;
    int ct   = idx >> 12;                       // 0..31
    uint32_t h4[4], l4v[4];
#pragma unroll
    for (int v = 0; v < 2; v++) {
        int nj = 2 * jp + v;
#pragma unroll
        for (int kh = 0; kh < 2; kh++) {
            int n = (g << 10) + ct * 32 + nj * 8 + (lane >> 2);
            int k = it * 16 + 2 * (lane & 3) + 8 * kh;
            split_pack(W_hh[(size_t)n * 256 + k], W_hh[(size_t)n * 256 + k + 1],
                       h4[v * 2 + kh], l4v[v * 2 + kh]);
        }
    }
    size_t base = (size_t)((((ct * 17 + it) * 4 + g) * 2 + jp) * 32 + lane) * 4;
    *(uint4*)&g_Wpk_hi[base] = make_uint4(h4[0], h4[1], h4[2], h4[3]);
    *(uint4*)&g_Wpk_lo[base] = make_uint4(l4v[0], l4v[1], l4v[2], l4v[3]);
}

// ---------------- prologue 4: fragment-pack W_hr ----------------
__global__ __launch_bounds__(256) void pack_whr(const float* __restrict__ W_hr)
{
    int idx = blockIdx.x * 256 + threadIdx.x;   // 0..65535
    int lane = idx & 31;
    int kc = (idx >> 5) & 63;
    int wr = (idx >> 11) & 3;
    int rt = idx >> 13;
    uint32_t h2[2], l2[2];
#pragma unroll
    for (int bh = 0; bh < 2; bh++) {
        int n = rt * 32 + wr * 8 + (lane >> 2);
        int k = kc * 16 + 2 * (lane & 3) + 8 * bh;
        split_pack(W_hr[(size_t)n * 1024 + k], W_hr[(size_t)n * 1024 + k + 1], h2[bh], l2[bh]);
    }
    size_t base = (size_t)((rt * 4 + wr) * 64 + kc) * 64 + lane * 2;
    *(uint2*)&g_Whrpk_hi[base] = make_uint2(h2[0], h2[1]);
    *(uint2*)&g_Whrpk_lo[base] = make_uint2(l2[0], l2[1]);
}

// ---------------- prologue 5: pair-pack x ----------------
__global__ __launch_bounds__(256) void pack_x(const float* __restrict__ x)
{
    int idx = blockIdx.x * 256 + threadIdx.x;   // 0..102399
    int m = idx & 511;
    int t = idx >> 9;
    const float* xr = x + ((size_t)m * SS + t) * 16;
    size_t base = ((size_t)t * 512 + m) * 8;
#pragma unroll
    for (int p = 0; p < 8; p++) {
        int q = (p < 4) ? 2 * p : 2 * (p - 4) + 1;
        uint32_t hi, lo;
        split_pack(xr[2 * p], xr[2 * p + 1], hi, lo);
        g_xpk_hi[base + q] = hi;
        g_xpk_lo[base + q] = lo;
    }
}

// ---------------- init (re-run every launch: determinism) ----------------
__global__ void init_state()
{
    int i = blockIdx.x * blockDim.x + threadIdx.x;
    if (i == 0) g_bar_count = 0u;
    if (i < BB * 16 * 8) {
        g_hpk_hi[i] = 0u;
        g_hpk_lo[i] = 0u;
    }
}

// ---------------- persistent-kernel phase helpers ----------------
__device__ __forceinline__ void g_loadA(uint2 aH[2], uint2 aL[2],
                                        int it, int t, int m0, int wid, int l4, int lq)
{
#pragma unroll
    for (int h = 0; h < 2; h++) {
        int row = m0 + wid * 16 + h * 8 + l4;
        if (it < 16) {
            size_t off = ((size_t)row * 16 + it) * 8 + lq * 2;
            aH[h] = __ldcg((const uint2*)(g_hpk_hi + off));
            aL[h] = __ldcg((const uint2*)(g_hpk_lo + off));
        } else {
            size_t off = ((size_t)t * 512 + row) * 8 + lq * 2;
            aH[h] = __ldcg((const uint2*)(g_xpk_hi + off));
            aL[h] = __ldcg((const uint2*)(g_xpk_lo + off));
        }
    }
}
// plain LDG (L1-cacheable): weight slice stays L1-resident across steps
__device__ __forceinline__ void g_loadB(uint4 bH[4][2], uint4 bL[4][2], int ct, int it, int lane)
{
#pragma unroll
    for (int g = 0; g < 4; g++) {
#pragma unroll
        for (int jp = 0; jp < 2; jp++) {
            size_t base = (size_t)((((ct * 17 + it) * 4 + g) * 2 + jp) * 32 + lane) * 4;
            bH[g][jp] = *(const uint4*)&g_Wpk_hi[base];
            bL[g][jp] = *(const uint4*)&g_Wpk_lo[base];
        }
    }
}
__device__ __forceinline__ void g_mma(float acc[4][4][4], uint2 aH[2], uint2 aL[2],
                                      uint4 bH[4][2], uint4 bL[4][2])
{
    uint32_t AH[4] = { aH[0].x, aH[1].x, aH[0].y, aH[1].y };
    uint32_t AL[4] = { aL[0].x, aL[1].x, aL[0].y, aL[1].y };
#pragma unroll
    for (int g = 0; g < 4; g++) {
#pragma unroll
        for (int jp = 0; jp < 2; jp++) {
            uint4 h4 = bH[g][jp];
            uint4 l4v = bL[g][jp];
            mma_bf16(acc[g][2 * jp + 0], AH, h4.x, h4.y);
            mma_bf16(acc[g][2 * jp + 0], AH, l4v.x, l4v.y);
            mma_bf16(acc[g][2 * jp + 0], AL, h4.x, h4.y);
            mma_bf16(acc[g][2 * jp + 1], AH, h4.z, h4.w);
            mma_bf16(acc[g][2 * jp + 1], AH, l4v.z, l4v.w);
            mma_bf16(acc[g][2 * jp + 1], AL, h4.z, h4.w);
        }
    }
}
__device__ __forceinline__ void p_loadA(uint2 aH[2], uint2 aL[2], int kc, int mbase, int l4, int lq)
{
#pragma unroll
    for (int h = 0; h < 2; h++) {
        int row = mbase + h * 8 + l4;
        size_t off = ((size_t)row * 64 + kc) * 8 + lq * 2;
        aH[h] = __ldcg((const uint2*)&g_hrawpk_hi[off]);
        aL[h] = __ldcg((const uint2*)&g_hrawpk_lo[off]);
    }
}
// __ldcg: keep proj weights OUT of L1 so gates weights stay resident
__device__ __forceinline__ void p_loadB(uint2& bh, uint2& bl, int rt, int wr, int kc, int lane)
{
    size_t base = (size_t)((rt * 4 + wr) * 64 + kc) * 64 + lane * 2;
    bh = __ldcg((const uint2*)&g_Whrpk_hi[base]);
    bl = __ldcg((const uint2*)&g_Whrpk_lo[base]);
}
__device__ __forceinline__ void p_mma(float acc[4], uint2 aH[2], uint2 aL[2], uint2 bh, uint2 bl)
{
    uint32_t AH[4] = { aH[0].x, aH[1].x, aH[0].y, aH[1].y };
    uint32_t AL[4] = { aL[0].x, aL[1].x, aL[0].y, aL[1].y };
    mma_bf16(acc, AH, bh.x, bh.y);
    mma_bf16(acc, AH, bl.x, bl.y);
    mma_bf16(acc, AL, bh.x, bh.y);
}

// ---------------- persistent recurrence ----------------
// gates map: 4 m-tiles (128 rows) x 32 col-tiles (32 j x 4 gates).
// smem: Zc tile 128x128 f32 (64KB) + c tile 128x32 f32 (16KB)
__global__ __launch_bounds__(256, 1) void lstm_persistent()
{
    extern __shared__ float smem[];
    float* sZc = smem;             // [ml 128][g*32+jl 128]
    float* sC  = smem + 128 * 128; // [ml 128][jl 32]

    int bid = blockIdx.x;
    // gates tile map
    int ct = bid & 31;
    int mt = bid >> 5;
    int m0 = mt * 128;
    // proj tile map
    int rt2 = bid & 7;
    int mt2 = bid >> 3;

    int tid = threadIdx.x;
    int wid = tid >> 5;
    int lane = tid & 31;
    int l4 = lane >> 2;
    int lq = lane & 3;

    // stage Zc tile into smem (once), zero c tile
    for (int idx = tid; idx < 128 * 128; idx += 256) {
        int ml = idx >> 7;
        int col = idx & 127;
        int g = col >> 5;
        int jl = col & 31;
        sZc[idx] = g_Zc[(size_t)(m0 + ml) * G4 + (g << 10) + ct * 32 + jl];
    }
    for (int idx = tid; idx < 128 * 32; idx += 256) sC[idx] = 0.0f;
    __syncthreads();

    unsigned int bar = 0;

    for (int t = 0; t < SS; t++) {
        // ================= gates phase =================
        {
            float acc[4][4][4];
#pragma unroll
            for (int g = 0; g < 4; g++)
#pragma unroll
                for (int nj = 0; nj < 4; nj++)
#pragma unroll
                    for (int q = 0; q < 4; q++) acc[g][nj][q] = 0.0f;

            uint2 aH0[2], aL0[2];
            uint2 aH1[2], aL1[2];
            uint4 bHa[4][2], bLa[4][2];
            uint4 bHb[4][2], bLb[4][2];

            g_loadA(aH0, aL0, 0, t, m0, wid, l4, lq);
#pragma unroll
            for (int it = 0; it < 17; it += 2) {
                g_loadB(bHa, bLa, ct, it, lane);
                if (it + 1 < 17) g_loadA(aH1, aL1, it + 1, t, m0, wid, l4, lq);
                g_mma(acc, aH0, aL0, bHa, bLa);
                if (it + 1 < 17) {
                    g_loadB(bHb, bLb, ct, it + 1, lane);
                    if (it + 2 < 17) g_loadA(aH0, aL0, it + 2, t, m0, wid, l4, lq);
                    g_mma(acc, aH1, aL1, bHb, bLb);
                }
            }

            // epilogue: + Zc(smem), LSTM cell (c in smem), write pair-packed hraw
#pragma unroll
            for (int h = 0; h < 2; h++) {
                int ml = wid * 16 + h * 8 + l4;
                int m = m0 + ml;
#pragma unroll
                for (int nj = 0; nj < 4; nj++) {
                    int jl = nj * 8 + 2 * lq;
                    float pre0[4], pre1[4];
#pragma unroll
                    for (int g = 0; g < 4; g++) {
                        float2 zc = *(const float2*)&sZc[ml * 128 + g * 32 + jl];
                        pre0[g] = acc[g][nj][2 * h + 0] + zc.x;
                        pre1[g] = acc[g][nj][2 * h + 1] + zc.y;
                    }
                    float2 cold = *(float2*)&sC[ml * 32 + jl];
                    float cn0 = sigf(pre0[1]) * cold.x + sigf(pre0[0]) * tanh_f(pre0[2]);
                    float cn1 = sigf(pre1[1]) * cold.y + sigf(pre1[0]) * tanh_f(pre1[2]);
                    *(float2*)&sC[ml * 32 + jl] = make_float2(cn0, cn1);
                    float hr0 = sigf(pre0[3]) * tanh_f(cn0);
                    float hr1 = sigf(pre1[3]) * tanh_f(cn1);
                    uint32_t hi, lo;
                    split_pack(hr0, hr1, hi, lo);
                    int q = 2 * lq + (nj & 1);
                    int kc = ct * 2 + (nj >> 1);
                    g_hrawpk_hi[((size_t)m * 64 + kc) * 8 + q] = hi;
                    g_hrawpk_lo[((size_t)m * 64 + kc) * 8 + q] = lo;
                }
            }
        }
        grid_bar(++bar * NCTA);

        // ================= projection phase =================
        {
            int wm = wid >> 2;
            int wr = wid & 3;
            int mbase = mt2 * 32 + wm * 16;

            float acc[4] = {0.0f, 0.0f, 0.0f, 0.0f};
            uint2 aH0[2], aL0[2], b0h, b0l;
            uint2 aH1[2], aL1[2], b1h, b1l;
            p_loadA(aH0, aL0, 0, mbase, l4, lq);
            p_loadB(b0h, b0l, rt2, wr, 0, lane);
#pragma unroll 8
            for (int kc = 0; kc < 64; kc += 2) {
                p_loadA(aH1, aL1, kc + 1, mbase, l4, lq);
                p_loadB(b1h, b1l, rt2, wr, kc + 1, lane);
                p_mma(acc, aH0, aL0, b0h, b0l);
                if (kc + 2 < 64) {
                    p_loadA(aH0, aL0, kc + 2, mbase, l4, lq);
                    p_loadB(b0h, b0l, rt2, wr, kc + 2, lane);
                }
                p_mma(acc, aH1, aL1, b1h, b1l);
            }

            int r = rt2 * 32 + wr * 8 + 2 * lq;
            int kc_h = rt2 * 2 + (wr >> 1);
            int q = 2 * lq + (wr & 1);
#pragma unroll
            for (int h = 0; h < 2; h++) {
                int m = mbase + h * 8 + l4;
                float v0 = acc[2 * h + 0];
                float v1 = acc[2 * h + 1];
                *(float2*)&g_hs[((size_t)m * SS + t) * PP + r] = make_float2(v0, v1);
                uint32_t hi, lo;
                split_pack(v0, v1, hi, lo);
                g_hpk_hi[((size_t)m * 16 + kc_h) * 8 + q] = hi;
                g_hpk_lo[((size_t)m * 16 + kc_h) * 8 + q] = lo;
            }
        }
        grid_bar(++bar * NCTA);
    }
}

// ---------------- output heads: LN + command logits + coords (warp per row) ----------------
__global__ __launch_bounds__(256) void head_kernel(
    const float* __restrict__ ln_g, const float* __restrict__ ln_b,
    const float* __restrict__ W_oc, const float* __restrict__ b_oc,
    const float* __restrict__ W_ox, const float* __restrict__ b_ox,
    const float* __restrict__ scale_p, float* __restrict__ out)
{
    int gw = (blockIdx.x * 256 + threadIdx.x) >> 5;
    int lane = threadIdx.x & 31;
    if (gw >= BB * SS) return;

    const float* hrow = g_hs + (size_t)gw * PP;
    float v[8];
#pragma unroll
    for (int q = 0; q < 2; q++) {
        float4 f = *reinterpret_cast<const float4*>(hrow + lane * 8 + q * 4);
        v[q * 4 + 0] = f.x;
        v[q * 4 + 1] = f.y;
        v[q * 4 + 2] = f.z;
        v[q * 4 + 3] = f.w;
    }
    float s = 0.0f;
    float s2 = 0.0f;
#pragma unroll
    for (int e = 0; e < 8; e++) {
        s += v[e];
        s2 = fmaf(v[e], v[e], s2);
    }
#pragma unroll
    for (int o = 16; o > 0; o >>= 1) {
        s  += __shfl_xor_sync(0xFFFFFFFFu, s, o);
        s2 += __shfl_xor_sync(0xFFFFFFFFu, s2, o);
    }
    float mean = s * (1.0f / 256.0f);
    float var = s2 * (1.0f / 256.0f) - mean * mean;
    float rstd = rsqrtf(var + 1e-5f);

    float hn[8];
#pragma unroll
    for (int e = 0; e < 8; e++) {
        int c = lane * 8 + e;
        hn[e] = (v[e] - mean) * rstd * ln_g[c] + ln_b[c];
    }

    float lgs[10];
#pragma unroll
    for (int cc = 0; cc < 10; cc++) {
        float p = 0.0f;
#pragma unroll
        for (int e = 0; e < 8; e++)
            p = fmaf(hn[e], W_oc[cc * 256 + lane * 8 + e], p);
#pragma unroll
        for (int o = 16; o > 0; o >>= 1) p += __shfl_xor_sync(0xFFFFFFFFu, p, o);
        p += b_oc[cc];
        lgs[cc] = p;
        if (lane == cc) out[(size_t)gw * 10 + cc] = p;
    }

    float csc = *scale_p;
    float* outc = out + (size_t)BB * SS * 10;
#pragma unroll
    for (int q = 0; q < 6; q++) {
        float p = 0.0f;
#pragma unroll
        for (int e = 0; e < 8; e++)
            p = fmaf(hn[e], W_ox[q * 266 + lane * 8 + e], p);
#pragma unroll
        for (int o = 16; o > 0; o >>= 1) p += __shfl_xor_sync(0xFFFFFFFFu, p, o);
#pragma unroll
        for (int cc = 0; cc < 10; cc++)
            p = fmaf(lgs[cc], W_ox[q * 266 + 256 + cc], p);
        p += b_ox[q];
        float z = tanh_f(p * csc);
        if (lane == q) outc[(size_t)gw * 6 + q] = z;
    }
}

// ---------------- launch ----------------
extern "C" void kernel_launch(void* const* d_in, const int* in_sizes, int n_in,
                              void* d_out, int out_size)
{
    const float* x      = (const float*)d_in[0];
    const float* ctx    = (const float*)d_in[1];
    const float* W_cmd  = (const float*)d_in[2];
    const float* b_cmd  = (const float*)d_in[3];
    const float* W_crd  = (const float*)d_in[4];
    const float* b_crd  = (const float*)d_in[5];
    const float* W_ih   = (const float*)d_in[6];
    const float* b_ih   = (const float*)d_in[7];
    const float* W_hh   = (const float*)d_in[8];
    const float* b_hh   = (const float*)d_in[9];
    const float* W_hr   = (const float*)d_in[10];
    const float* ln_g   = (const float*)d_in[11];
    const float* ln_b   = (const float*)d_in[12];
    const float* W_oc   = (const float*)d_in[13];
    const float* b_oc   = (const float*)d_in[14];
    const float* W_ox   = (const float*)d_in[15];
    const float* b_ox   = (const float*)d_in[16];
    const float* cscale = (const float*)d_in[17];
    float* out = (float*)d_out;

    static bool attr_set = false;
    if (!attr_set) {
        cudaFuncSetAttribute(lstm_persistent,
                             cudaFuncAttributeMaxDynamicSharedMemorySize,
                             (128 * 128 + 128 * 32) * (int)sizeof(float));
        attr_set = true;
    }

    prep_weff<<<G4, 128>>>(W_ih, b_ih, W_cmd, b_cmd, W_crd, b_crd, b_hh);
    prep_zc<<<dim3(G4 / 64, BB / 64), 256>>>(ctx, W_ih);
    pack_whh<<<512, 256>>>(W_hh);
    pack_whr<<<256, 256>>>(W_hr);
    pack_x<<<400, 256>>>(x);
    init_state<<<(BB * 16 * 8 + 255) / 256, 256>>>();

    lstm_persistent<<<NCTA, 256, (128 * 128 + 128 * 32) * sizeof(float)>>>();

    head_kernel<<<(BB * SS * 32 + 255) / 256, 256>>>(
        ln_g, ln_b, W_oc, b_oc, W_ox, b_ox, cscale, out);
}

// round 10
// speedup vs baseline: 2.9084x; 1.2662x over previous
#include <cuda_runtime.h>
#include <cuda_fp16.h>
#include <cstdint>
#include <math.h>

#define BB   512
#define SS   200
#define DD   1024
#define PP   256
#define G4   4096
#define DIN  1280
#define NCTA 128

// ---------------- scratch (device globals; no allocation allowed) ----------------
__device__ float g_bias[G4];                       // folded bias
__device__ float g_Zc[(size_t)BB * G4];            // (512,4096) context+bias
__device__ float g_hs[(size_t)BB * SS * PP];       // all projected hiddens (heads)
__device__ unsigned int g_bar_count;               // grid barrier (cumulative)

// gates weights, fragment-packed fp16 for L1 residency:
// uint4 index b4 = (((ct*17+it)*4+g)*2+jp)*32 + lane ; .x/.y = nj=2jp (klo,khi), .z/.w = nj=2jp+1
__device__ __align__(16) uint32_t g_Wpk[32 * 17 * 4 * 2 * 32 * 4];
// proj weights fp16: [((rt*4+wr)*64+kc)][lane 32][reg 2] uint32
__device__ __align__(16) uint32_t g_Whrpk[8 * 4 * 64 * 64];
// pair-packed fp16 activations: h [m][kc16][q8], hraw [m][kc64][q8], x [t][m][q8]
__device__ __align__(16) uint32_t g_hpk[(size_t)BB * 16 * 8];
__device__ __align__(16) uint32_t g_hrawpk[(size_t)BB * 64 * 8];
__device__ __align__(16) uint32_t g_xpk[(size_t)SS * BB * 8];

// ---------------- helpers ----------------
__device__ __forceinline__ float sigf(float x) { return 1.0f / (1.0f + __expf(-x)); }
__device__ __forceinline__ float tanh_f(float x) {
    float e = __expf(-2.0f * fabsf(x));
    float t = (1.0f - e) / (1.0f + e);
    return copysignf(t, x);
}
__device__ __forceinline__ uint32_t pack_h2(float e0, float e1) {
    __half2 h = __floats2half2_rn(e0, e1);
    return *reinterpret_cast<uint32_t*>(&h);
}
__device__ __forceinline__ void mma_f16(float* d, const uint32_t* a, uint32_t b0, uint32_t b1) {
    asm volatile("mma.sync.aligned.m16n8k16.row.col.f32.f16.f16.f32 "
                 "{%0,%1,%2,%3}, {%4,%5,%6,%7}, {%8,%9}, {%0,%1,%2,%3};"
                 : "+f"(d[0]), "+f"(d[1]), "+f"(d[2]), "+f"(d[3])
                 : "r"(a[0]), "r"(a[1]), "r"(a[2]), "r"(a[3]), "r"(b0), "r"(b1));
}
// deterministic grid barrier: cumulative counter, target = bar_id * NCTA
__device__ __forceinline__ void grid_bar(unsigned int target) {
    __syncthreads();
    if (threadIdx.x == 0) {
        __threadfence();
        atomicAdd(&g_bar_count, 1u);
        while (atomicAdd(&g_bar_count, 0u) < target) { }
        __threadfence();
    }
    __syncthreads();
}

// ---------------- prologue 1: W_eff reduction -> fragment-packed (it=16), bias ----------------
__global__ __launch_bounds__(128) void prep_weff(
    const float* __restrict__ W_ih, const float* __restrict__ b_ih,
    const float* __restrict__ W_cmd, const float* __restrict__ b_cmd,
    const float* __restrict__ W_crd, const float* __restrict__ b_crd,
    const float* __restrict__ b_hh)
{
    int j = blockIdx.x;            // 0..4095 (gate-major row)
    int t = threadIdx.x;
    __shared__ float red[17][128];

    float acc[17];
#pragma unroll
    for (int c = 0; c < 17; c++) acc[c] = 0.0f;

    const float* wrow = W_ih + (size_t)j * DIN;
    for (int k = t; k < DD; k += 128) {
        float w = wrow[k];
#pragma unroll
        for (int c = 0; c < 10; c++) acc[c]      = fmaf(w, W_cmd[k * 10 + c], acc[c]);
#pragma unroll
        for (int c = 0; c < 6; c++)  acc[10 + c] = fmaf(w, W_crd[k * 6 + c], acc[10 + c]);
        acc[16] = fmaf(w, b_cmd[k] + b_crd[k], acc[16]);
    }
#pragma unroll
    for (int c = 0; c < 17; c++) red[c][t] = acc[c];
    __syncthreads();
    for (int off = 64; off > 0; off >>= 1) {
        if (t < off) {
#pragma unroll
            for (int c = 0; c < 17; c++) red[c][t] += red[c][t + off];
        }
        __syncthreads();
    }
    if (t == 0) {
        int g     = j >> 10;
        int jglob = j & 1023;
        int ct    = jglob >> 5;
        int rem   = jglob & 31;
        int nj    = rem >> 3;
        int l4    = rem & 7;
        int jp    = nj >> 1;
        int v     = nj & 1;
#pragma unroll
        for (int lq = 0; lq < 4; lq++) {
#pragma unroll
            for (int kh = 0; kh < 2; kh++) {
                size_t b4 = (size_t)((((ct * 17 + 16) * 4 + g) * 2 + jp) * 32 + (l4 * 4 + lq));
                size_t u = b4 * 4 + v * 2 + kh;
                g_Wpk[u] = pack_h2(red[2 * lq + 8 * kh][0], red[2 * lq + 8 * kh + 1][0]);
            }
        }
        g_bias[j] = red[16][0] + b_ih[j] + b_hh[j];
    }
}

// ---------------- prologue 2: Zc = ctx @ W_ih[:,1024:]^T + bias ----------------
__global__ __launch_bounds__(256) void prep_zc(
    const float* __restrict__ ctx, const float* __restrict__ W_ih)
{
    __shared__ float sA[64][17];
    __shared__ float sB[64][17];
    int n0 = blockIdx.x * 64;
    int m0 = blockIdx.y * 64;
    int tid = threadIdx.x;
    int tx = tid & 15;
    int ty = tid >> 4;

    float acc[4][4];
#pragma unroll
    for (int i = 0; i < 4; i++)
#pragma unroll
        for (int j = 0; j < 4; j++) acc[i][j] = 0.0f;

    for (int k0 = 0; k0 < 256; k0 += 16) {
        __syncthreads();
#pragma unroll
        for (int q = 0; q < 4; q++) {
            int e = q * 256 + tid;
            int r = e >> 4;
            int c = e & 15;
            sA[r][c] = ctx[(size_t)(m0 + r) * 256 + k0 + c];
            sB[r][c] = W_ih[(size_t)(n0 + r) * DIN + 1024 + k0 + c];
        }
        __syncthreads();
#pragma unroll
        for (int kk = 0; kk < 16; kk++) {
            float a[4];
            float b[4];
#pragma unroll
            for (int i = 0; i < 4; i++) a[i] = sA[ty + 16 * i][kk];
#pragma unroll
            for (int j = 0; j < 4; j++) b[j] = sB[tx + 16 * j][kk];
#pragma unroll
            for (int i = 0; i < 4; i++)
#pragma unroll
                for (int j = 0; j < 4; j++) acc[i][j] = fmaf(a[i], b[j], acc[i][j]);
        }
    }
#pragma unroll
    for (int i = 0; i < 4; i++) {
        int m = m0 + ty + 16 * i;
#pragma unroll
        for (int j = 0; j < 4; j++) {
            int n = n0 + tx + 16 * j;
            g_Zc[(size_t)m * G4 + n] = acc[i][j] + g_bias[n];
        }
    }
}

// ---------------- prologue 3: fragment-pack W_hh fp16 (it 0..15) ----------------
__global__ __launch_bounds__(256) void pack_whh(const float* __restrict__ W_hh)
{
    int idx = blockIdx.x * 256 + threadIdx.x;   // 0..131071
    int lane = idx & 31;
    int jp   = (idx >> 5) & 1;
    int g    = (idx >> 6) & 3;
    int it   = (idx >> 8) & 15;
    int ct   = idx >> 12;                       // 0..31
    uint32_t h4[4];
#pragma unroll
    for (int v = 0; v < 2; v++) {
        int nj = 2 * jp + v;
#pragma unroll
        for (int kh = 0; kh < 2; kh++) {
            int n = (g << 10) + ct * 32 + nj * 8 + (lane >> 2);
            int k = it * 16 + 2 * (lane & 3) + 8 * kh;
            h4[v * 2 + kh] = pack_h2(W_hh[(size_t)n * 256 + k], W_hh[(size_t)n * 256 + k + 1]);
        }
    }
    size_t base = (size_t)((((ct * 17 + it) * 4 + g) * 2 + jp) * 32 + lane) * 4;
    *(uint4*)&g_Wpk[base] = make_uint4(h4[0], h4[1], h4[2], h4[3]);
}

// ---------------- prologue 4: fragment-pack W_hr fp16 ----------------
__global__ __launch_bounds__(256) void pack_whr(const float* __restrict__ W_hr)
{
    int idx = blockIdx.x * 256 + threadIdx.x;   // 0..65535
    int lane = idx & 31;
    int kc = (idx >> 5) & 63;
    int wr = (idx >> 11) & 3;
    int rt = idx >> 13;
    uint32_t h2[2];
#pragma unroll
    for (int bh = 0; bh < 2; bh++) {
        int n = rt * 32 + wr * 8 + (lane >> 2);
        int k = kc * 16 + 2 * (lane & 3) + 8 * bh;
        h2[bh] = pack_h2(W_hr[(size_t)n * 1024 + k], W_hr[(size_t)n * 1024 + k + 1]);
    }
    size_t base = (size_t)((rt * 4 + wr) * 64 + kc) * 64 + lane * 2;
    *(uint2*)&g_Whrpk[base] = make_uint2(h2[0], h2[1]);
}

// ---------------- prologue 5: pair-pack x fp16 ----------------
__global__ __launch_bounds__(256) void pack_x(const float* __restrict__ x)
{
    int idx = blockIdx.x * 256 + threadIdx.x;   // 0..102399
    int m = idx & 511;
    int t = idx >> 9;
    const float* xr = x + ((size_t)m * SS + t) * 16;
    size_t base = ((size_t)t * 512 + m) * 8;
#pragma unroll
    for (int p = 0; p < 8; p++) {
        int q = (p < 4) ? 2 * p : 2 * (p - 4) + 1;
        g_xpk[base + q] = pack_h2(xr[2 * p], xr[2 * p + 1]);
    }
}

// ---------------- init (re-run every launch: determinism) ----------------
__global__ void init_state()
{
    int i = blockIdx.x * blockDim.x + threadIdx.x;
    if (i == 0) g_bar_count = 0u;
    if (i < BB * 16 * 8) g_hpk[i] = 0u;
}

// ---------------- persistent-kernel phase helpers ----------------
__device__ __forceinline__ void g_loadA(uint2 aH[2], int it, int t, int m0, int wid, int l4, int lq)
{
#pragma unroll
    for (int h = 0; h < 2; h++) {
        int row = m0 + wid * 16 + h * 8 + l4;
        if (it < 16) {
            size_t off = ((size_t)row * 16 + it) * 8 + lq * 2;
            aH[h] = __ldcg((const uint2*)(g_hpk + off));
        } else {
            size_t off = ((size_t)t * 512 + row) * 8 + lq * 2;
            aH[h] = __ldcg((const uint2*)(g_xpk + off));
        }
    }
}
// plain LDG (L1-cacheable): weight slice (~70KB/CTA) stays L1-resident across steps
__device__ __forceinline__ void g_loadB(uint4 bH[4][2], int ct, int it, int lane)
{
#pragma unroll
    for (int g = 0; g < 4; g++) {
#pragma unroll
        for (int jp = 0; jp < 2; jp++) {
            size_t base = (size_t)((((ct * 17 + it) * 4 + g) * 2 + jp) * 32 + lane) * 4;
            bH[g][jp] = *(const uint4*)&g_Wpk[base];
        }
    }
}
__device__ __forceinline__ void g_mma(float acc[4][4][4], uint2 aH[2], uint4 bH[4][2])
{
    uint32_t AH[4] = { aH[0].x, aH[1].x, aH[0].y, aH[1].y };
#pragma unroll
    for (int g = 0; g < 4; g++) {
#pragma unroll
        for (int jp = 0; jp < 2; jp++) {
            uint4 h4 = bH[g][jp];
            mma_f16(acc[g][2 * jp + 0], AH, h4.x, h4.y);
            mma_f16(acc[g][2 * jp + 1], AH, h4.z, h4.w);
        }
    }
}
__device__ __forceinline__ void p_loadA(uint2 aH[2], int kc, int mbase, int l4, int lq)
{
#pragma unroll
    for (int h = 0; h < 2; h++) {
        int row = mbase + h * 8 + l4;
        size_t off = ((size_t)row * 64 + kc) * 8 + lq * 2;
        aH[h] = __ldcg((const uint2*)&g_hrawpk[off]);
    }
}
// __ldcg: keep proj weights OUT of L1 so gates weights stay resident
__device__ __forceinline__ void p_loadB(uint2& bh, int rt, int wr, int kc, int lane)
{
    size_t base = (size_t)((rt * 4 + wr) * 64 + kc) * 64 + lane * 2;
    bh = __ldcg((const uint2*)&g_Whrpk[base]);
}
__device__ __forceinline__ void p_mma(float acc[4], uint2 aH[2], uint2 bh)
{
    uint32_t AH[4] = { aH[0].x, aH[1].x, aH[0].y, aH[1].y };
    mma_f16(acc, AH, bh.x, bh.y);
}

// ---------------- persistent recurrence ----------------
// gates map: 4 m-tiles (128 rows) x 32 col-tiles (32 j x 4 gates).
// smem: Zc tile 128x128 f32 (64KB) + c tile 128x32 f32 (16KB)
__global__ __launch_bounds__(256, 1) void lstm_persistent()
{
    extern __shared__ float smem[];
    float* sZc = smem;             // [ml 128][g*32+jl 128]
    float* sC  = smem + 128 * 128; // [ml 128][jl 32]

    int bid = blockIdx.x;
    // gates tile map
    int ct = bid & 31;
    int mt = bid >> 5;
    int m0 = mt * 128;
    // proj tile map
    int rt2 = bid & 7;
    int mt2 = bid >> 3;

    int tid = threadIdx.x;
    int wid = tid >> 5;
    int lane = tid & 31;
    int l4 = lane >> 2;
    int lq = lane & 3;

    // stage Zc tile into smem (once), zero c tile
    for (int idx = tid; idx < 128 * 128; idx += 256) {
        int ml = idx >> 7;
        int col = idx & 127;
        int g = col >> 5;
        int jl = col & 31;
        sZc[idx] = g_Zc[(size_t)(m0 + ml) * G4 + (g << 10) + ct * 32 + jl];
    }
    for (int idx = tid; idx < 128 * 32; idx += 256) sC[idx] = 0.0f;
    __syncthreads();

    unsigned int bar = 0;

    for (int t = 0; t < SS; t++) {
        // ================= gates phase =================
        {
            float acc[4][4][4];
#pragma unroll
            for (int g = 0; g < 4; g++)
#pragma unroll
                for (int nj = 0; nj < 4; nj++)
#pragma unroll
                    for (int q = 0; q < 4; q++) acc[g][nj][q] = 0.0f;

            uint2 aH0[2], aH1[2];
            uint4 bHa[4][2], bHb[4][2];

            g_loadA(aH0, 0, t, m0, wid, l4, lq);
#pragma unroll
            for (int it = 0; it < 17; it += 2) {
                g_loadB(bHa, ct, it, lane);
                if (it + 1 < 17) g_loadA(aH1, it + 1, t, m0, wid, l4, lq);
                g_mma(acc, aH0, bHa);
                if (it + 1 < 17) {
                    g_loadB(bHb, ct, it + 1, lane);
                    if (it + 2 < 17) g_loadA(aH0, it + 2, t, m0, wid, l4, lq);
                    g_mma(acc, aH1, bHb);
                }
            }

            // epilogue: + Zc(smem), LSTM cell (c in smem), write pair-packed hraw
#pragma unroll
            for (int h = 0; h < 2; h++) {
                int ml = wid * 16 + h * 8 + l4;
                int m = m0 + ml;
#pragma unroll
                for (int nj = 0; nj < 4; nj++) {
                    int jl = nj * 8 + 2 * lq;
                    float pre0[4], pre1[4];
#pragma unroll
                    for (int g = 0; g < 4; g++) {
                        float2 zc = *(const float2*)&sZc[ml * 128 + g * 32 + jl];
                        pre0[g] = acc[g][nj][2 * h + 0] + zc.x;
                        pre1[g] = acc[g][nj][2 * h + 1] + zc.y;
                    }
                    float2 cold = *(float2*)&sC[ml * 32 + jl];
                    float cn0 = sigf(pre0[1]) * cold.x + sigf(pre0[0]) * tanh_f(pre0[2]);
                    float cn1 = sigf(pre1[1]) * cold.y + sigf(pre1[0]) * tanh_f(pre1[2]);
                    *(float2*)&sC[ml * 32 + jl] = make_float2(cn0, cn1);
                    float hr0 = sigf(pre0[3]) * tanh_f(cn0);
                    float hr1 = sigf(pre1[3]) * tanh_f(cn1);
                    int q = 2 * lq + (nj & 1);
                    int kc = ct * 2 + (nj >> 1);
                    g_hrawpk[((size_t)m * 64 + kc) * 8 + q] = pack_h2(hr0, hr1);
                }
            }
        }
        grid_bar(++bar * NCTA);

        // ================= projection phase =================
        {
            int wm = wid >> 2;
            int wr = wid & 3;
            int mbase = mt2 * 32 + wm * 16;

            float acc[4] = {0.0f, 0.0f, 0.0f, 0.0f};
            uint2 aH0[2], b0h;
            uint2 aH1[2], b1h;
            p_loadA(aH0, 0, mbase, l4, lq);
            p_loadB(b0h, rt2, wr, 0, lane);
#pragma unroll 8
            for (int kc = 0; kc < 64; kc += 2) {
                p_loadA(aH1, kc + 1, mbase, l4, lq);
                p_loadB(b1h, rt2, wr, kc + 1, lane);
                p_mma(acc, aH0, b0h);
                if (kc + 2 < 64) {
                    p_loadA(aH0, kc + 2, mbase, l4, lq);
                    p_loadB(b0h, rt2, wr, kc + 2, lane);
                }
                p_mma(acc, aH1, b1h);
            }

            int r = rt2 * 32 + wr * 8 + 2 * lq;
            int kc_h = rt2 * 2 + (wr >> 1);
            int q = 2 * lq + (wr & 1);
#pragma unroll
            for (int h = 0; h < 2; h++) {
                int m = mbase + h * 8 + l4;
                float v0 = acc[2 * h + 0];
                float v1 = acc[2 * h + 1];
                *(float2*)&g_hs[((size_t)m * SS + t) * PP + r] = make_float2(v0, v1);
                g_hpk[((size_t)m * 16 + kc_h) * 8 + q] = pack_h2(v0, v1);
            }
        }
        grid_bar(++bar * NCTA);
    }
}

// ---------------- output heads: LN + command logits + coords (warp per row) ----------------
__global__ __launch_bounds__(256) void head_kernel(
    const float* __restrict__ ln_g, const float* __restrict__ ln_b,
    const float* __restrict__ W_oc, const float* __restrict__ b_oc,
    const float* __restrict__ W_ox, const float* __restrict__ b_ox,
    const float* __restrict__ scale_p, float* __restrict__ out)
{
    int gw = (blockIdx.x * 256 + threadIdx.x) >> 5;
    int lane = threadIdx.x & 31;
    if (gw >= BB * SS) return;

    const float* hrow = g_hs + (size_t)gw * PP;
    float v[8];
#pragma unroll
    for (int q = 0; q < 2; q++) {
        float4 f = *reinterpret_cast<const float4*>(hrow + lane * 8 + q * 4);
        v[q * 4 + 0] = f.x;
        v[q * 4 + 1] = f.y;
        v[q * 4 + 2] = f.z;
        v[q * 4 + 3] = f.w;
    }
    float s = 0.0f;
    float s2 = 0.0f;
#pragma unroll
    for (int e = 0; e < 8; e++) {
        s += v[e];
        s2 = fmaf(v[e], v[e], s2);
    }
#pragma unroll
    for (int o = 16; o > 0; o >>= 1) {
        s  += __shfl_xor_sync(0xFFFFFFFFu, s, o);
        s2 += __shfl_xor_sync(0xFFFFFFFFu, s2, o);
    }
    float mean = s * (1.0f / 256.0f);
    float var = s2 * (1.0f / 256.0f) - mean * mean;
    float rstd = rsqrtf(var + 1e-5f);

    float hn[8];
#pragma unroll
    for (int e = 0; e < 8; e++) {
        int c = lane * 8 + e;
        hn[e] = (v[e] - mean) * rstd * ln_g[c] + ln_b[c];
    }

    float lgs[10];
#pragma unroll
    for (int cc = 0; cc < 10; cc++) {
        float p = 0.0f;
#pragma unroll
        for (int e = 0; e < 8; e++)
            p = fmaf(hn[e], W_oc[cc * 256 + lane * 8 + e], p);
#pragma unroll
        for (int o = 16; o > 0; o >>= 1) p += __shfl_xor_sync(0xFFFFFFFFu, p, o);
        p += b_oc[cc];
        lgs[cc] = p;
        if (lane == cc) out[(size_t)gw * 10 + cc] = p;
    }

    float csc = *scale_p;
    float* outc = out + (size_t)BB * SS * 10;
#pragma unroll
    for (int q = 0; q < 6; q++) {
        float p = 0.0f;
#pragma unroll
        for (int e = 0; e < 8; e++)
            p = fmaf(hn[e], W_ox[q * 266 + lane * 8 + e], p);
#pragma unroll
        for (int o = 16; o > 0; o >>= 1) p += __shfl_xor_sync(0xFFFFFFFFu, p, o);
#pragma unroll
        for (int cc = 0; cc < 10; cc++)
            p = fmaf(lgs[cc], W_ox[q * 266 + 256 + cc], p);
        p += b_ox[q];
        float z = tanh_f(p * csc);
        if (lane == q) outc[(size_t)gw * 6 + q] = z;
    }
}

// ---------------- launch ----------------
extern "C" void kernel_launch(void* const* d_in, const int* in_sizes, int n_in,
                              void* d_out, int out_size)
{
    const float* x      = (const float*)d_in[0];
    const float* ctx    = (const float*)d_in[1];
    const float* W_cmd  = (const float*)d_in[2];
    const float* b_cmd  = (const float*)d_in[3];
    const float* W_crd  = (const float*)d_in[4];
    const float* b_crd  = (const float*)d_in[5];
    const float* W_ih   = (const float*)d_in[6];
    const float* b_ih   = (const float*)d_in[7];
    const float* W_hh   = (const float*)d_in[8];
    const float* b_hh   = (const float*)d_in[9];
    const float* W_hr   = (const float*)d_in[10];
    const float* ln_g   = (const float*)d_in[11];
    const float* ln_b   = (const float*)d_in[12];
    const float* W_oc   = (const float*)d_in[13];
    const float* b_oc   = (const float*)d_in[14];
    const float* W_ox   = (const float*)d_in[15];
    const float* b_ox   = (const float*)d_in[16];
    const float* cscale = (const float*)d_in[17];
    float* out = (float*)d_out;

    static bool attr_set = false;
    if (!attr_set) {
        cudaFuncSetAttribute(lstm_persistent,
                             cudaFuncAttributeMaxDynamicSharedMemorySize,
                             (128 * 128 + 128 * 32) * (int)sizeof(float));
        attr_set = true;
    }

    prep_weff<<<G4, 128>>>(W_ih, b_ih, W_cmd, b_cmd, W_crd, b_crd, b_hh);
    prep_zc<<<dim3(G4 / 64, BB / 64), 256>>>(ctx, W_ih);
    pack_whh<<<512, 256>>>(W_hh);
    pack_whr<<<256, 256>>>(W_hr);
    pack_x<<<400, 256>>>(x);
    init_state<<<(BB * 16 * 8 + 255) / 256, 256>>>();

    lstm_persistent<<<NCTA, 256, (128 * 128 + 128 * 32) * sizeof(float)>>>();

    head_kernel<<<(BB * SS * 32 + 255) / 256, 256>>>(
        ln_g, ln_b, W_oc, b_oc, W_ox, b_ox, cscale, out);
}

// round 11
// speedup vs baseline: 3.2587x; 1.1204x over previous
#include <cuda_runtime.h>
#include <cuda_fp16.h>
#include <cstdint>
#include <math.h>

#define BB   512
#define SS   200
#define DD   1024
#define PP   256
#define G4   4096
#define DIN  1280
#define NCTA 128

#define WG_U32 17408   // gates weight slice per CTA in u32 (17*4*2*32*4)
#define WP_U32 16384   // proj weight slice per CTA in u32 (4*64*64)
#define ZC_F32 16384   // Zc tile (128 x 128)
#define SMEM_BYTES ((WG_U32 + WP_U32) * 4 + ZC_F32 * 4)

// ---------------- scratch (device globals; no allocation allowed) ----------------
__device__ float g_bias[G4];                       // folded bias
__device__ float g_Zc[(size_t)BB * G4];            // (512,4096) context+bias
__device__ float g_hs[(size_t)BB * SS * PP];       // all projected hiddens (heads)
__device__ unsigned int g_bar_count;               // grid barrier (cumulative)

// gates weights, fragment-packed fp16:
// u32 index = (((ct*17+it)*4+g)*2+jp)*32 + lane)*4 + reg
__device__ __align__(16) uint32_t g_Wpk[32 * 17 * 4 * 2 * 32 * 4];
// proj weights fp16: [((rt*4+wr)*64+kc)][lane 32][reg 2] u32
__device__ __align__(16) uint32_t g_Whrpk[8 * 4 * 64 * 64];
// pair-packed fp16 activations: h [m][kc16][q8], hraw [m][kc64][q8], x [t][m][q8]
__device__ __align__(16) uint32_t g_hpk[(size_t)BB * 16 * 8];
__device__ __align__(16) uint32_t g_hrawpk[(size_t)BB * 64 * 8];
__device__ __align__(16) uint32_t g_xpk[(size_t)SS * BB * 8];

// ---------------- helpers ----------------
__device__ __forceinline__ float sigf(float x) { return 1.0f / (1.0f + __expf(-x)); }
__device__ __forceinline__ float tanh_f(float x) {
    float e = __expf(-2.0f * fabsf(x));
    float t = (1.0f - e) / (1.0f + e);
    return copysignf(t, x);
}
__device__ __forceinline__ uint32_t pack_h2(float e0, float e1) {
    __half2 h = __floats2half2_rn(e0, e1);
    return *reinterpret_cast<uint32_t*>(&h);
}
__device__ __forceinline__ void mma_f16(float* d, const uint32_t* a, uint32_t b0, uint32_t b1) {
    asm volatile("mma.sync.aligned.m16n8k16.row.col.f32.f16.f16.f32 "
                 "{%0,%1,%2,%3}, {%4,%5,%6,%7}, {%8,%9}, {%0,%1,%2,%3};"
                 : "+f"(d[0]), "+f"(d[1]), "+f"(d[2]), "+f"(d[3])
                 : "r"(a[0]), "r"(a[1]), "r"(a[2]), "r"(a[3]), "r"(b0), "r"(b1));
}
// deterministic grid barrier: cumulative counter, target = bar_id * NCTA
__device__ __forceinline__ void grid_bar(unsigned int target) {
    __syncthreads();
    if (threadIdx.x == 0) {
        __threadfence();
        atomicAdd(&g_bar_count, 1u);
        while (atomicAdd(&g_bar_count, 0u) < target) { }
        __threadfence();
    }
    __syncthreads();
}

// ---------------- prologue 1: W_eff reduction -> fragment-packed (it=16), bias ----------------
__global__ __launch_bounds__(128) void prep_weff(
    const float* __restrict__ W_ih, const float* __restrict__ b_ih,
    const float* __restrict__ W_cmd, const float* __restrict__ b_cmd,
    const float* __restrict__ W_crd, const float* __restrict__ b_crd,
    const float* __restrict__ b_hh)
{
    int j = blockIdx.x;            // 0..4095 (gate-major row)
    int t = threadIdx.x;
    __shared__ float red[17][128];

    float acc[17];
#pragma unroll
    for (int c = 0; c < 17; c++) acc[c] = 0.0f;

    const float* wrow = W_ih + (size_t)j * DIN;
    for (int k = t; k < DD; k += 128) {
        float w = wrow[k];
#pragma unroll
        for (int c = 0; c < 10; c++) acc[c]      = fmaf(w, W_cmd[k * 10 + c], acc[c]);
#pragma unroll
        for (int c = 0; c < 6; c++)  acc[10 + c] = fmaf(w, W_crd[k * 6 + c], acc[10 + c]);
        acc[16] = fmaf(w, b_cmd[k] + b_crd[k], acc[16]);
    }
#pragma unroll
    for (int c = 0; c < 17; c++) red[c][t] = acc[c];
    __syncthreads();
    for (int off = 64; off > 0; off >>= 1) {
        if (t < off) {
#pragma unroll
            for (int c = 0; c < 17; c++) red[c][t] += red[c][t + off];
        }
        __syncthreads();
    }
    if (t == 0) {
        int g     = j >> 10;
        int jglob = j & 1023;
        int ct    = jglob >> 5;
        int rem   = jglob & 31;
        int nj    = rem >> 3;
        int l4    = rem & 7;
        int jp    = nj >> 1;
        int v     = nj & 1;
#pragma unroll
        for (int lq = 0; lq < 4; lq++) {
#pragma unroll
            for (int kh = 0; kh < 2; kh++) {
                size_t b4 = (size_t)((((ct * 17 + 16) * 4 + g) * 2 + jp) * 32 + (l4 * 4 + lq));
                size_t u = b4 * 4 + v * 2 + kh;
                g_Wpk[u] = pack_h2(red[2 * lq + 8 * kh][0], red[2 * lq + 8 * kh + 1][0]);
            }
        }
        g_bias[j] = red[16][0] + b_ih[j] + b_hh[j];
    }
}

// ---------------- prologue 2: Zc = ctx @ W_ih[:,1024:]^T + bias ----------------
__global__ __launch_bounds__(256) void prep_zc(
    const float* __restrict__ ctx, const float* __restrict__ W_ih)
{
    __shared__ float sA[64][17];
    __shared__ float sB[64][17];
    int n0 = blockIdx.x * 64;
    int m0 = blockIdx.y * 64;
    int tid = threadIdx.x;
    int tx = tid & 15;
    int ty = tid >> 4;

    float acc[4][4];
#pragma unroll
    for (int i = 0; i < 4; i++)
#pragma unroll
        for (int j = 0; j < 4; j++) acc[i][j] = 0.0f;

    for (int k0 = 0; k0 < 256; k0 += 16) {
        __syncthreads();
#pragma unroll
        for (int q = 0; q < 4; q++) {
            int e = q * 256 + tid;
            int r = e >> 4;
            int c = e & 15;
            sA[r][c] = ctx[(size_t)(m0 + r) * 256 + k0 + c];
            sB[r][c] = W_ih[(size_t)(n0 + r) * DIN + 1024 + k0 + c];
        }
        __syncthreads();
#pragma unroll
        for (int kk = 0; kk < 16; kk++) {
            float a[4];
            float b[4];
#pragma unroll
            for (int i = 0; i < 4; i++) a[i] = sA[ty + 16 * i][kk];
#pragma unroll
            for (int j = 0; j < 4; j++) b[j] = sB[tx + 16 * j][kk];
#pragma unroll
            for (int i = 0; i < 4; i++)
#pragma unroll
                for (int j = 0; j < 4; j++) acc[i][j] = fmaf(a[i], b[j], acc[i][j]);
        }
    }
#pragma unroll
    for (int i = 0; i < 4; i++) {
        int m = m0 + ty + 16 * i;
#pragma unroll
        for (int j = 0; j < 4; j++) {
            int n = n0 + tx + 16 * j;
            g_Zc[(size_t)m * G4 + n] = acc[i][j] + g_bias[n];
        }
    }
}

// ---------------- prologue 3: fragment-pack W_hh fp16 (it 0..15) ----------------
__global__ __launch_bounds__(256) void pack_whh(const float* __restrict__ W_hh)
{
    int idx = blockIdx.x * 256 + threadIdx.x;   // 0..131071
    int lane = idx & 31;
    int jp   = (idx >> 5) & 1;
    int g    = (idx >> 6) & 3;
    int it   = (idx >> 8) & 15;
    int ct   = idx >> 12;                       // 0..31
    uint32_t h4[4];
#pragma unroll
    for (int v = 0; v < 2; v++) {
        int nj = 2 * jp + v;
#pragma unroll
        for (int kh = 0; kh < 2; kh++) {
            int n = (g << 10) + ct * 32 + nj * 8 + (lane >> 2);
            int k = it * 16 + 2 * (lane & 3) + 8 * kh;
            h4[v * 2 + kh] = pack_h2(W_hh[(size_t)n * 256 + k], W_hh[(size_t)n * 256 + k + 1]);
        }
    }
    size_t base = (size_t)((((ct * 17 + it) * 4 + g) * 2 + jp) * 32 + lane) * 4;
    *(uint4*)&g_Wpk[base] = make_uint4(h4[0], h4[1], h4[2], h4[3]);
}

// ---------------- prologue 4: fragment-pack W_hr fp16 ----------------
__global__ __launch_bounds__(256) void pack_whr(const float* __restrict__ W_hr)
{
    int idx = blockIdx.x * 256 + threadIdx.x;   // 0..65535
    int lane = idx & 31;
    int kc = (idx >> 5) & 63;
    int wr = (idx >> 11) & 3;
    int rt = idx >> 13;
    uint32_t h2[2];
#pragma unroll
    for (int bh = 0; bh < 2; bh++) {
        int n = rt * 32 + wr * 8 + (lane >> 2);
        int k = kc * 16 + 2 * (lane & 3) + 8 * bh;
        h2[bh] = pack_h2(W_hr[(size_t)n * 1024 + k], W_hr[(size_t)n * 1024 + k + 1]);
    }
    size_t base = (size_t)((rt * 4 + wr) * 64 + kc) * 64 + lane * 2;
    *(uint2*)&g_Whrpk[base] = make_uint2(h2[0], h2[1]);
}

// ---------------- prologue 5: pair-pack x fp16 ----------------
__global__ __launch_bounds__(256) void pack_x(const float* __restrict__ x)
{
    int idx = blockIdx.x * 256 + threadIdx.x;   // 0..102399
    int m = idx & 511;
    int t = idx >> 9;
    const float* xr = x + ((size_t)m * SS + t) * 16;
    size_t base = ((size_t)t * 512 + m) * 8;
#pragma unroll
    for (int p = 0; p < 8; p++) {
        int q = (p < 4) ? 2 * p : 2 * (p - 4) + 1;
        g_xpk[base + q] = pack_h2(xr[2 * p], xr[2 * p + 1]);
    }
}

// ---------------- init (re-run every launch: determinism) ----------------
__global__ void init_state()
{
    int i = blockIdx.x * blockDim.x + threadIdx.x;
    if (i == 0) g_bar_count = 0u;
    if (i < BB * 16 * 8) g_hpk[i] = 0u;
}

// ---------------- persistent-kernel phase helpers ----------------
__device__ __forceinline__ void g_loadA(uint2 aH[2], int it, int t, int m0, int wid, int l4, int lq)
{
#pragma unroll
    for (int h = 0; h < 2; h++) {
        int row = m0 + wid * 16 + h * 8 + l4;
        if (it < 16) {
            size_t off = ((size_t)row * 16 + it) * 8 + lq * 2;
            aH[h] = __ldcg((const uint2*)(g_hpk + off));
        } else {
            size_t off = ((size_t)t * 512 + row) * 8 + lq * 2;
            aH[h] = __ldcg((const uint2*)(g_xpk + off));
        }
    }
}
__device__ __forceinline__ void p_loadA(uint2 aH[2], int kc, int mbase, int l4, int lq)
{
#pragma unroll
    for (int h = 0; h < 2; h++) {
        int row = mbase + h * 8 + l4;
        size_t off = ((size_t)row * 64 + kc) * 8 + lq * 2;
        aH[h] = __ldcg((const uint2*)&g_hrawpk[off]);
    }
}

// ---------------- persistent recurrence ----------------
// gates map: 4 m-tiles (128 rows) x 32 col-tiles (32 j x 4 gates).
// smem: gates W slice (68KB) + proj W slice (64KB) + Zc tile (64KB). c state in registers.
__global__ __launch_bounds__(256, 1) void lstm_persistent()
{
    extern __shared__ uint32_t smemw[];
    uint32_t* sWg = smemw;                         // WG_U32
    uint32_t* sWp = smemw + WG_U32;                // WP_U32
    float*    sZc = (float*)(smemw + WG_U32 + WP_U32); // ZC_F32

    int bid = blockIdx.x;
    // gates tile map
    int ct = bid & 31;
    int mt = bid >> 5;
    int m0 = mt * 128;
    // proj tile map
    int rt2 = bid & 7;
    int mt2 = bid >> 3;

    int tid = threadIdx.x;
    int wid = tid >> 5;
    int lane = tid & 31;
    int l4 = lane >> 2;
    int lq = lane & 3;

    // ---- one-time staging: weight slices + Zc tile into smem ----
    {
        const uint4* srcg = (const uint4*)(g_Wpk + (size_t)ct * WG_U32);
        uint4* dstg = (uint4*)sWg;
        for (int i = tid; i < WG_U32 / 4; i += 256) dstg[i] = srcg[i];
        const uint4* srcp = (const uint4*)(g_Whrpk + (size_t)rt2 * WP_U32);
        uint4* dstp = (uint4*)sWp;
        for (int i = tid; i < WP_U32 / 4; i += 256) dstp[i] = srcp[i];
    }
    for (int idx = tid; idx < 128 * 128; idx += 256) {
        int ml = idx >> 7;
        int col = idx & 127;
        int g = col >> 5;
        int jl = col & 31;
        sZc[idx] = g_Zc[(size_t)(m0 + ml) * G4 + (g << 10) + ct * 32 + jl];
    }
    // cell state lives in registers: creg[h][nj][0/1] for this thread's fixed (m,j) coords
    float creg[2][4][2];
#pragma unroll
    for (int h = 0; h < 2; h++)
#pragma unroll
        for (int nj = 0; nj < 4; nj++) {
            creg[h][nj][0] = 0.0f;
            creg[h][nj][1] = 0.0f;
        }
    __syncthreads();

    unsigned int bar = 0;

    for (int t = 0; t < SS; t++) {
        // ================= gates phase =================
        {
            float acc[4][4][4];
#pragma unroll
            for (int g = 0; g < 4; g++)
#pragma unroll
                for (int nj = 0; nj < 4; nj++)
#pragma unroll
                    for (int q = 0; q < 4; q++) acc[g][nj][q] = 0.0f;

            uint2 aH0[2], aH1[2];
            g_loadA(aH0, 0, t, m0, wid, l4, lq);
#pragma unroll
            for (int it = 0; it < 17; ++it) {
                if (it + 1 < 17) g_loadA(aH1, it + 1, t, m0, wid, l4, lq);
                uint32_t AH[4] = { aH0[0].x, aH0[1].x, aH0[0].y, aH0[1].y };
#pragma unroll
                for (int g = 0; g < 4; g++) {
#pragma unroll
                    for (int jp = 0; jp < 2; jp++) {
                        uint4 h4 = *(const uint4*)&sWg[((((it * 4 + g) * 2 + jp) * 32 + lane)) * 4];
                        mma_f16(acc[g][2 * jp + 0], AH, h4.x, h4.y);
                        mma_f16(acc[g][2 * jp + 1], AH, h4.z, h4.w);
                    }
                }
                aH0[0] = aH1[0];
                aH0[1] = aH1[1];
            }

            // epilogue: + Zc(smem), LSTM cell (c in regs), write pair-packed hraw
#pragma unroll
            for (int h = 0; h < 2; h++) {
                int ml = wid * 16 + h * 8 + l4;
                int m = m0 + ml;
#pragma unroll
                for (int nj = 0; nj < 4; nj++) {
                    int jl = nj * 8 + 2 * lq;
                    float pre0[4], pre1[4];
#pragma unroll
                    for (int g = 0; g < 4; g++) {
                        float2 zc = *(const float2*)&sZc[ml * 128 + g * 32 + jl];
                        pre0[g] = acc[g][nj][2 * h + 0] + zc.x;
                        pre1[g] = acc[g][nj][2 * h + 1] + zc.y;
                    }
                    float cn0 = sigf(pre0[1]) * creg[h][nj][0] + sigf(pre0[0]) * tanh_f(pre0[2]);
                    float cn1 = sigf(pre1[1]) * creg[h][nj][1] + sigf(pre1[0]) * tanh_f(pre1[2]);
                    creg[h][nj][0] = cn0;
                    creg[h][nj][1] = cn1;
                    float hr0 = sigf(pre0[3]) * tanh_f(cn0);
                    float hr1 = sigf(pre1[3]) * tanh_f(cn1);
                    int q = 2 * lq + (nj & 1);
                    int kc = ct * 2 + (nj >> 1);
                    g_hrawpk[((size_t)m * 64 + kc) * 8 + q] = pack_h2(hr0, hr1);
                }
            }
        }
        grid_bar(++bar * NCTA);

        // ================= projection phase =================
        {
            int wm = wid >> 2;
            int wr = wid & 3;
            int mbase = mt2 * 32 + wm * 16;

            float acc[4] = {0.0f, 0.0f, 0.0f, 0.0f};
            uint2 aH0[2], aH1[2];
            p_loadA(aH0, 0, mbase, l4, lq);
#pragma unroll 8
            for (int kc = 0; kc < 64; ++kc) {
                if (kc + 1 < 64) p_loadA(aH1, kc + 1, mbase, l4, lq);
                uint32_t AH[4] = { aH0[0].x, aH0[1].x, aH0[0].y, aH0[1].y };
                uint2 bh = *(const uint2*)&sWp[(wr * 64 + kc) * 64 + lane * 2];
                mma_f16(acc, AH, bh.x, bh.y);
                aH0[0] = aH1[0];
                aH0[1] = aH1[1];
            }

            int r = rt2 * 32 + wr * 8 + 2 * lq;
            int kc_h = rt2 * 2 + (wr >> 1);
            int q = 2 * lq + (wr & 1);
#pragma unroll
            for (int h = 0; h < 2; h++) {
                int m = mbase + h * 8 + l4;
                float v0 = acc[2 * h + 0];
                float v1 = acc[2 * h + 1];
                *(float2*)&g_hs[((size_t)m * SS + t) * PP + r] = make_float2(v0, v1);
                g_hpk[((size_t)m * 16 + kc_h) * 8 + q] = pack_h2(v0, v1);
            }
        }
        grid_bar(++bar * NCTA);
    }
}

// ---------------- output heads: LN + command logits + coords (warp per row) ----------------
__global__ __launch_bounds__(256) void head_kernel(
    const float* __restrict__ ln_g, const float* __restrict__ ln_b,
    const float* __restrict__ W_oc, const float* __restrict__ b_oc,
    const float* __restrict__ W_ox, const float* __restrict__ b_ox,
    const float* __restrict__ scale_p, float* __restrict__ out)
{
    int gw = (blockIdx.x * 256 + threadIdx.x) >> 5;
    int lane = threadIdx.x & 31;
    if (gw >= BB * SS) return;

    const float* hrow = g_hs + (size_t)gw * PP;
    float v[8];
#pragma unroll
    for (int q = 0; q < 2; q++) {
        float4 f = *reinterpret_cast<const float4*>(hrow + lane * 8 + q * 4);
        v[q * 4 + 0] = f.x;
        v[q * 4 + 1] = f.y;
        v[q * 4 + 2] = f.z;
        v[q * 4 + 3] = f.w;
    }
    float s = 0.0f;
    float s2 = 0.0f;
#pragma unroll
    for (int e = 0; e < 8; e++) {
        s += v[e];
        s2 = fmaf(v[e], v[e], s2);
    }
#pragma unroll
    for (int o = 16; o > 0; o >>= 1) {
        s  += __shfl_xor_sync(0xFFFFFFFFu, s, o);
        s2 += __shfl_xor_sync(0xFFFFFFFFu, s2, o);
    }
    float mean = s * (1.0f / 256.0f);
    float var = s2 * (1.0f / 256.0f) - mean * mean;
    float rstd = rsqrtf(var + 1e-5f);

    float hn[8];
#pragma unroll
    for (int e = 0; e < 8; e++) {
        int c = lane * 8 + e;
        hn[e] = (v[e] - mean) * rstd * ln_g[c] + ln_b[c];
    }

    float lgs[10];
#pragma unroll
    for (int cc = 0; cc < 10; cc++) {
        float p = 0.0f;
#pragma unroll
        for (int e = 0; e < 8; e++)
            p = fmaf(hn[e], W_oc[cc * 256 + lane * 8 + e], p);
#pragma unroll
        for (int o = 16; o > 0; o >>= 1) p += __shfl_xor_sync(0xFFFFFFFFu, p, o);
        p += b_oc[cc];
        lgs[cc] = p;
        if (lane == cc) out[(size_t)gw * 10 + cc] = p;
    }

    float csc = *scale_p;
    float* outc = out + (size_t)BB * SS * 10;
#pragma unroll
    for (int q = 0; q < 6; q++) {
        float p = 0.0f;
#pragma unroll
        for (int e = 0; e < 8; e++)
            p = fmaf(hn[e], W_ox[q * 266 + lane * 8 + e], p);
#pragma unroll
        for (int o = 16; o > 0; o >>= 1) p += __shfl_xor_sync(0xFFFFFFFFu, p, o);
#pragma unroll
        for (int cc = 0; cc < 10; cc++)
            p = fmaf(lgs[cc], W_ox[q * 266 + 256 + cc], p);
        p += b_ox[q];
        float z = tanh_f(p * csc);
        if (lane == q) outc[(size_t)gw * 6 + q] = z;
    }
}

// ---------------- launch ----------------
extern "C" void kernel_launch(void* const* d_in, const int* in_sizes, int n_in,
                              void* d_out, int out_size)
{
    const float* x      = (const float*)d_in[0];
    const float* ctx    = (const float*)d_in[1];
    const float* W_cmd  = (const float*)d_in[2];
    const float* b_cmd  = (const float*)d_in[3];
    const float* W_crd  = (const float*)d_in[4];
    const float* b_crd  = (const float*)d_in[5];
    const float* W_ih   = (const float*)d_in[6];
    const float* b_ih   = (const float*)d_in[7];
    const float* W_hh   = (const float*)d_in[8];
    const float* b_hh   = (const float*)d_in[9];
    const float* W_hr   = (const float*)d_in[10];
    const float* ln_g   = (const float*)d_in[11];
    const float* ln_b   = (const float*)d_in[12];
    const float* W_oc   = (const float*)d_in[13];
    const float* b_oc   = (const float*)d_in[14];
    const float* W_ox   = (const float*)d_in[15];
    const float* b_ox   = (const float*)d_in[16];
    const float* cscale = (const float*)d_in[17];
    float* out = (float*)d_out;

    static bool attr_set = false;
    if (!attr_set) {
        cudaFuncSetAttribute(lstm_persistent,
                             cudaFuncAttributeMaxDynamicSharedMemorySize,
                             SMEM_BYTES);
        attr_set = true;
    }

    prep_weff<<<G4, 128>>>(W_ih, b_ih, W_cmd, b_cmd, W_crd, b_crd, b_hh);
    prep_zc<<<dim3(G4 / 64, BB / 64), 256>>>(ctx, W_ih);
    pack_whh<<<512, 256>>>(W_hh);
    pack_whr<<<256, 256>>>(W_hr);
    pack_x<<<400, 256>>>(x);
    init_state<<<(BB * 16 * 8 + 255) / 256, 256>>>();

    lstm_persistent<<<NCTA, 256, SMEM_BYTES>>>();

    head_kernel<<<(BB * SS * 32 + 255) / 256, 256>>>(
        ln_g, ln_b, W_oc, b_oc, W_ox, b_ox, cscale, out);
}